// round 6
// baseline (speedup 1.0000x reference)
#include <cuda_runtime.h>
#include <cuda_bf16.h>
#include <cstdint>

#define BB   8
#define LL   8192
#define DIM  512
#define NH   8
#define DH   64
#define KS   13
#define NS   6
#define DIL  2

// ---------------------------------------------------------------------------
// Device scratch (static only)
// ---------------------------------------------------------------------------
__device__ float g_q[(size_t)BB * NH * LL * DH];
__device__ float g_k[(size_t)BB * NH * LL * DH];
__device__ float g_v[(size_t)BB * NH * LL * DH];
__device__ __nv_bfloat16 g_ah[(size_t)BB * LL * DIM];   // hidden hi split [M,K]
__device__ __nv_bfloat16 g_al[(size_t)BB * LL * DIM];   // hidden lo split
__device__ __nv_bfloat16 g_wh[3][DIM * DIM];            // W^T hi  [N,K]
__device__ __nv_bfloat16 g_wl[3][DIM * DIM];            // W^T lo  [N,K]

// ---------------------------------------------------------------------------
// Baseline-PTX helpers
// ---------------------------------------------------------------------------
__device__ __forceinline__ uint32_t smem_u32(const void* p) {
    uint32_t a;
    asm("{ .reg .u64 t; cvta.to.shared.u64 t, %1; cvt.u32.u64 %0, t; }" : "=r"(a) : "l"(p));
    return a;
}
__device__ __forceinline__ void cp_async16(uint32_t saddr, const void* gptr) {
    asm volatile("cp.async.cg.shared.global [%0], [%1], 16;"
                 :: "r"(saddr), "l"(__cvta_generic_to_global(gptr)) : "memory");
}
#define CP_COMMIT() asm volatile("cp.async.commit_group;" ::: "memory")
#define CP_WAIT(n)  asm volatile("cp.async.wait_group %0;" :: "n"(n) : "memory")

__device__ __forceinline__ void ldsm_x4(uint32_t* r, uint32_t addr) {
    asm volatile("ldmatrix.sync.aligned.m8n8.x4.shared.b16 {%0,%1,%2,%3}, [%4];"
                 : "=r"(r[0]), "=r"(r[1]), "=r"(r[2]), "=r"(r[3]) : "r"(addr));
}
__device__ __forceinline__ void mma16816(float* c, const uint32_t* a, const uint32_t* b) {
    asm volatile("mma.sync.aligned.m16n8k16.row.col.f32.bf16.bf16.f32 "
                 "{%0,%1,%2,%3}, {%4,%5,%6,%7}, {%8,%9}, {%0,%1,%2,%3};"
                 : "+f"(c[0]), "+f"(c[1]), "+f"(c[2]), "+f"(c[3])
                 : "r"(a[0]), "r"(a[1]), "r"(a[2]), "r"(a[3]), "r"(b[0]), "r"(b[1]));
}

// ---------------------------------------------------------------------------
// Split hidden states fp32 -> bf16 hi/lo
// ---------------------------------------------------------------------------
__global__ void convert_a_kernel(const float* __restrict__ A) {
    size_t i = ((size_t)blockIdx.x * 256 + threadIdx.x) * 4;
    float4 x = *(const float4*)(A + i);
    __nv_bfloat16 h0 = __float2bfloat16(x.x), h1 = __float2bfloat16(x.y);
    __nv_bfloat16 h2 = __float2bfloat16(x.z), h3 = __float2bfloat16(x.w);
    __nv_bfloat16 l0 = __float2bfloat16(x.x - __bfloat162float(h0));
    __nv_bfloat16 l1 = __float2bfloat16(x.y - __bfloat162float(h1));
    __nv_bfloat16 l2 = __float2bfloat16(x.z - __bfloat162float(h2));
    __nv_bfloat16 l3 = __float2bfloat16(x.w - __bfloat162float(h3));
    union { __nv_bfloat16 b[4]; uint2 u; } ph, pl;
    ph.b[0] = h0; ph.b[1] = h1; ph.b[2] = h2; ph.b[3] = h3;
    pl.b[0] = l0; pl.b[1] = l1; pl.b[2] = l2; pl.b[3] = l3;
    *(uint2*)(g_ah + i) = ph.u;
    *(uint2*)(g_al + i) = pl.u;
}

// ---------------------------------------------------------------------------
// Transpose + split W [K,N] -> W^T [N,K] bf16 hi/lo
// ---------------------------------------------------------------------------
__global__ void convert_w_kernel(const float* __restrict__ Wq,
                                 const float* __restrict__ Wk,
                                 const float* __restrict__ Wv) {
    const int z = blockIdx.z;
    const float* W = (z == 0) ? Wq : ((z == 1) ? Wk : Wv);
    __shared__ float t[32][33];
    const int n0 = blockIdx.x * 32, k0 = blockIdx.y * 32;
    #pragma unroll
    for (int j = 0; j < 32; j += 8)
        t[threadIdx.y + j][threadIdx.x] = W[(size_t)(k0 + threadIdx.y + j) * DIM + n0 + threadIdx.x];
    __syncthreads();
    #pragma unroll
    for (int j = 0; j < 32; j += 8) {
        float v = t[threadIdx.x][threadIdx.y + j];
        __nv_bfloat16 h = __float2bfloat16(v);
        __nv_bfloat16 l = __float2bfloat16(v - __bfloat162float(h));
        size_t o = (size_t)(n0 + threadIdx.y + j) * DIM + k0 + threadIdx.x;
        g_wh[z][o] = h;
        g_wl[z][o] = l;
    }
}

// ---------------------------------------------------------------------------
// HMMA bf16 GEMM (3-term split): C = Ah*Bh + Ah*Bl + Al*Bh, fp32 accum.
// CTA 128x128, 256 threads (8 warps, 2x4 of 64x32), BK=32,
// 3-stage cp.async ring (32KB/stage, 96KB) -> 2 CTAs/SM, 16 warps/SM.
// Tiles per stage: Ah|Al|Bh|Bl, each 128 x 32 bf16 (8KB), row=64B,
// swizzle: chunk j ^ ((row>>1)&3).
// Term-major MMA ordering: acc reuse distance = 16 MMAs (chains pipelined).
// ---------------------------------------------------------------------------
#define TILE_B   8192
#define STAGE_B  (4 * TILE_B)     // 32KB
#define NSTG     3
#define KSTAGES  16               // 512 / 32

__global__ void __launch_bounds__(256, 2)
qkv_mma_gemm(const float* __restrict__ bq, const float* __restrict__ bk,
             const float* __restrict__ bv)
{
    extern __shared__ __align__(1024) char dsm[];
    __shared__ float s_bias[128];

    const int tid  = threadIdx.x;
    const int wid  = tid >> 5;
    const int lane = tid & 31;
    const int wm   = wid >> 2;       // 0..1  (64-row slabs)
    const int wn   = wid & 3;        // 0..3  (32-col slabs)
    const int nt   = blockIdx.x & 3;
    const int z    = blockIdx.x >> 2;
    const int mt   = blockIdx.y;

    const uint32_t sbase = smem_u32(dsm);

    const float* bias = (z == 0) ? bq : ((z == 1) ? bk : bv);
    const float scale = (z == 0) ? 0.125f : 1.0f;
    float* outp       = (z == 0) ? g_q : ((z == 1) ? g_k : g_v);
    const __nv_bfloat16* srcs[4] = { g_ah + (size_t)mt * 128 * DIM,
                                     g_al + (size_t)mt * 128 * DIM,
                                     g_wh[z] + (size_t)nt * 128 * DIM,
                                     g_wl[z] + (size_t)nt * 128 * DIM };

    if (tid < 128) s_bias[tid] = bias[nt * 128 + tid];

    // ---- stage loader: 4 tiles x (128 rows x 4 sixteen-byte chunks) ----
    auto load_stage = [&](int kt, int buf) {
        const uint32_t sb = sbase + (uint32_t)buf * STAGE_B;
        #pragma unroll
        for (int tile = 0; tile < 4; ++tile) {
            const __nv_bfloat16* src = srcs[tile] + kt * 32;
            #pragma unroll
            for (int it = 0; it < 2; ++it) {
                const int c = it * 256 + tid;
                const int r = c >> 2, j = c & 3;
                const uint32_t soff = sb + (uint32_t)tile * TILE_B +
                                      (uint32_t)r * 64 + (uint32_t)((j ^ ((r >> 1) & 3)) << 4);
                cp_async16(soff, src + (size_t)r * DIM + j * 8);
            }
        }
        CP_COMMIT();
    };

    float acc[4][4][4];
    #pragma unroll
    for (int mi = 0; mi < 4; ++mi)
        #pragma unroll
        for (int ni = 0; ni < 4; ++ni)
            #pragma unroll
            for (int q = 0; q < 4; ++q) acc[mi][ni][q] = 0.f;

    load_stage(0, 0);
    load_stage(1, 1);

    // ldmatrix address components
    const int arow  = wm * 64 + (lane & 15);                             // + mi*16
    const int ahalf = lane >> 4;                                         // k16 half chunk
    const int brow_base = wn * 32 + ((lane >> 3) & 1) * 8 + (lane & 7);  // + np*16
    const int bchunk = lane >> 4;

    for (int kt = 0; kt < KSTAGES; ++kt) {
        if (kt < KSTAGES - 1) { CP_WAIT(1); } else { CP_WAIT(0); }
        __syncthreads();
        if (kt + 2 < KSTAGES) load_stage(kt + 2, (kt + 2) % NSTG);

        const uint32_t sb = sbase + (uint32_t)(kt % NSTG) * STAGE_B;
        const uint32_t aH = sb, aL = sb + TILE_B, bH = sb + 2 * TILE_B, bL = sb + 3 * TILE_B;

        #pragma unroll
        for (int ks = 0; ks < 2; ++ks) {
            uint32_t ahf[4][4], alf[4][4];
            uint32_t bhf[4][2], blf[4][2];
            #pragma unroll
            for (int mi = 0; mi < 4; ++mi) {
                const int r = arow + mi * 16;
                const int j = ks * 2 + ahalf;
                const uint32_t off = (uint32_t)r * 64 + (uint32_t)((j ^ ((r >> 1) & 3)) << 4);
                ldsm_x4(ahf[mi], aH + off);
                ldsm_x4(alf[mi], aL + off);
            }
            #pragma unroll
            for (int np = 0; np < 2; ++np) {     // pairs of n8 blocks
                const int r = brow_base + np * 16;
                const int j = ks * 2 + bchunk;
                const uint32_t off = (uint32_t)r * 64 + (uint32_t)((j ^ ((r >> 1) & 3)) << 4);
                uint32_t th[4], tl[4];
                ldsm_x4(th, bH + off);
                ldsm_x4(tl, bL + off);
                bhf[np * 2 + 0][0] = th[0]; bhf[np * 2 + 0][1] = th[2];
                bhf[np * 2 + 1][0] = th[1]; bhf[np * 2 + 1][1] = th[3];
                blf[np * 2 + 0][0] = tl[0]; blf[np * 2 + 0][1] = tl[2];
                blf[np * 2 + 1][0] = tl[1]; blf[np * 2 + 1][1] = tl[3];
            }
            // term-major ordering: acc reuse distance = 16 MMAs
            #pragma unroll
            for (int mi = 0; mi < 4; ++mi)
                #pragma unroll
                for (int ni = 0; ni < 4; ++ni)
                    mma16816(acc[mi][ni], ahf[mi], bhf[ni]);
            #pragma unroll
            for (int mi = 0; mi < 4; ++mi)
                #pragma unroll
                for (int ni = 0; ni < 4; ++ni)
                    mma16816(acc[mi][ni], ahf[mi], blf[ni]);
            #pragma unroll
            for (int mi = 0; mi < 4; ++mi)
                #pragma unroll
                for (int ni = 0; ni < 4; ++ni)
                    mma16816(acc[mi][ni], alf[mi], bhf[ni]);
        }
    }

    // ---- epilogue: bias + scale, scatter to head-major [B,H,L,DH] ----
    const int g = lane >> 2, tig = lane & 3;
    #pragma unroll
    for (int mi = 0; mi < 4; ++mi) {
        #pragma unroll
        for (int half = 0; half < 2; ++half) {
            const int m = mt * 128 + wm * 64 + mi * 16 + g + half * 8;
            const int b = m >> 13;
            const int l = m & (LL - 1);
            #pragma unroll
            for (int ni = 0; ni < 4; ++ni) {
                const int nl = wn * 32 + ni * 8 + 2 * tig;
                const int n  = nt * 128 + nl;
                const int h  = n >> 6, d = n & 63;
                float2 r2;
                r2.x = (acc[mi][ni][half * 2 + 0] + s_bias[nl + 0]) * scale;
                r2.y = (acc[mi][ni][half * 2 + 1] + s_bias[nl + 1]) * scale;
                *(float2*)&outp[(((size_t)b * NH + h) * LL + l) * DH + d] = r2;
            }
        }
    }
}

// ---------------------------------------------------------------------------
// NA1D attention (unchanged — 196us)
// ---------------------------------------------------------------------------
#define QT   128
#define SPAN 152
#define PAD  68

__global__ void __launch_bounds__(128, 4)
na1d_kernel(const float* __restrict__ rpb, float* __restrict__ out)
{
    __shared__ float kv[SPAN][PAD];
    __shared__ float s_rpb[2 * KS - 1];

    const int tid = threadIdx.x;
    const int bh  = blockIdx.y;
    const int b   = bh >> 3;
    const int h   = bh & 7;
    const int l0  = blockIdx.x << 7;
    const int i   = l0 + tid;

    if (tid < 2 * KS - 1) s_rpb[tid] = rpb[h * (2 * KS - 1) + tid];

    int ws, ps;
    if (i < NS * DIL) {
        ws = i & 1;
        ps = (KS - 1) - (i >> 1);
    } else if (i + NS * DIL >= LL) {
        ws = LL - KS * DIL + (i & 1);
        ps = (LL - 1 - i) >> 1;
    } else {
        ws = i - NS * DIL;
        ps = NS;
    }

    const int lo = (l0 >= NS * DIL) ? (l0 - NS * DIL) : 0;
    const int himax = l0 + QT - 1 + NS * DIL;
    const int hi = (himax <= LL - 1) ? himax : (LL - 1);
    const int n4 = (hi - lo + 1) * (DH / 4);
    const int r0 = ws - lo;
    const size_t base = (size_t)bh * LL * DH;

    {
        const float4* src = (const float4*)(g_k + base + (size_t)lo * DH);
        for (int tt = tid; tt < n4; tt += QT) {
            const int r = tt >> 4, c = tt & 15;
            *(float4*)&kv[r][c << 2] = src[tt];
        }
    }
    float4 q[16];
    {
        const float4* qp = (const float4*)(g_q + base + (size_t)i * DH);
        #pragma unroll
        for (int d = 0; d < 16; ++d) q[d] = qp[d];
    }
    __syncthreads();

    float sc[KS];
    #pragma unroll
    for (int j = 0; j < KS; ++j) {
        const float* kr = kv[r0 + DIL * j];
        float s = 0.f;
        #pragma unroll
        for (int d = 0; d < 16; ++d) {
            const float4 k4 = *(const float4*)&kr[d << 2];
            s = fmaf(q[d].x, k4.x, s);
            s = fmaf(q[d].y, k4.y, s);
            s = fmaf(q[d].z, k4.z, s);
            s = fmaf(q[d].w, k4.w, s);
        }
        sc[j] = s + s_rpb[ps + j];
    }

    float mx = sc[0];
    #pragma unroll
    for (int j = 1; j < KS; ++j) mx = fmaxf(mx, sc[j]);
    float sum = 0.f;
    #pragma unroll
    for (int j = 0; j < KS; ++j) { sc[j] = __expf(sc[j] - mx); sum += sc[j]; }
    const float rinv = 1.f / sum;

    __syncthreads();

    {
        const float4* src = (const float4*)(g_v + base + (size_t)lo * DH);
        for (int tt = tid; tt < n4; tt += QT) {
            const int r = tt >> 4, c = tt & 15;
            *(float4*)&kv[r][c << 2] = src[tt];
        }
    }
    __syncthreads();

    float4 o[16];
    #pragma unroll
    for (int d = 0; d < 16; ++d) o[d] = make_float4(0.f, 0.f, 0.f, 0.f);

    #pragma unroll
    for (int j = 0; j < KS; ++j) {
        const float p = sc[j];
        const float* vr = kv[r0 + DIL * j];
        #pragma unroll
        for (int d = 0; d < 16; ++d) {
            const float4 v4 = *(const float4*)&vr[d << 2];
            o[d].x = fmaf(p, v4.x, o[d].x);
            o[d].y = fmaf(p, v4.y, o[d].y);
            o[d].z = fmaf(p, v4.z, o[d].z);
            o[d].w = fmaf(p, v4.w, o[d].w);
        }
    }

    float* op = out + ((size_t)b * LL + i) * DIM + h * DH;
    #pragma unroll
    for (int d = 0; d < 16; ++d) {
        float4 r = o[d];
        r.x *= rinv; r.y *= rinv; r.z *= rinv; r.w *= rinv;
        *(float4*)&op[d << 2] = r;
    }
}

// ---------------------------------------------------------------------------
extern "C" void kernel_launch(void* const* d_in, const int* in_sizes, int n_in,
                              void* d_out, int out_size)
{
    const float* hs  = (const float*)d_in[0];
    const float* Wq  = (const float*)d_in[1];
    const float* bq  = (const float*)d_in[2];
    const float* Wk  = (const float*)d_in[3];
    const float* bk  = (const float*)d_in[4];
    const float* Wv  = (const float*)d_in[5];
    const float* bv  = (const float*)d_in[6];
    const float* rpb = (const float*)d_in[7];
    float* out = (float*)d_out;

    const int dyn_smem = NSTG * STAGE_B;   // 96KB
    cudaFuncSetAttribute(qkv_mma_gemm, cudaFuncAttributeMaxDynamicSharedMemorySize, dyn_smem);

    convert_a_kernel<<<32768, 256>>>(hs);
    convert_w_kernel<<<dim3(16, 16, 3), dim3(32, 8)>>>(Wq, Wk, Wv);
    qkv_mma_gemm<<<dim3(12, 512), 256, dyn_smem>>>(bq, bk, bv);
    na1d_kernel<<<dim3(LL / QT, BB * NH), 128>>>(rpb, out);
}

// round 7
// speedup vs baseline: 1.4758x; 1.4758x over previous
#include <cuda_runtime.h>
#include <cuda_bf16.h>
#include <cstdint>

#define BB   8
#define LL   8192
#define DIM  512
#define NH   8
#define DH   64
#define KS   13
#define NS   6
#define DIL  2

// ---------------------------------------------------------------------------
// Device scratch (static only)
// ---------------------------------------------------------------------------
__device__ float g_q[(size_t)BB * NH * LL * DH];
__device__ float g_k[(size_t)BB * NH * LL * DH];
__device__ float g_v[(size_t)BB * NH * LL * DH];
__device__ __nv_bfloat16 g_ah[(size_t)BB * LL * DIM];   // hidden hi split [M,K]
__device__ __nv_bfloat16 g_al[(size_t)BB * LL * DIM];   // hidden lo split
__device__ __nv_bfloat16 g_wh[3][DIM * DIM];            // W^T hi  [N,K]
__device__ __nv_bfloat16 g_wl[3][DIM * DIM];            // W^T lo  [N,K]

// ---------------------------------------------------------------------------
// Baseline-PTX helpers
// ---------------------------------------------------------------------------
__device__ __forceinline__ uint32_t smem_u32(const void* p) {
    uint32_t a;
    asm("{ .reg .u64 t; cvta.to.shared.u64 t, %1; cvt.u32.u64 %0, t; }" : "=r"(a) : "l"(p));
    return a;
}
__device__ __forceinline__ void cp_async16(uint32_t saddr, const void* gptr) {
    asm volatile("cp.async.cg.shared.global [%0], [%1], 16;"
                 :: "r"(saddr), "l"(__cvta_generic_to_global(gptr)) : "memory");
}
#define CP_COMMIT() asm volatile("cp.async.commit_group;" ::: "memory")
#define CP_WAIT(n)  asm volatile("cp.async.wait_group %0;" :: "n"(n) : "memory")

__device__ __forceinline__ void ldsm_x4(uint32_t* r, uint32_t addr) {
    asm volatile("ldmatrix.sync.aligned.m8n8.x4.shared.b16 {%0,%1,%2,%3}, [%4];"
                 : "=r"(r[0]), "=r"(r[1]), "=r"(r[2]), "=r"(r[3]) : "r"(addr));
}
__device__ __forceinline__ void mma16816(float* c, const uint32_t* a, const uint32_t* b) {
    asm volatile("mma.sync.aligned.m16n8k16.row.col.f32.bf16.bf16.f32 "
                 "{%0,%1,%2,%3}, {%4,%5,%6,%7}, {%8,%9}, {%0,%1,%2,%3};"
                 : "+f"(c[0]), "+f"(c[1]), "+f"(c[2]), "+f"(c[3])
                 : "r"(a[0]), "r"(a[1]), "r"(a[2]), "r"(a[3]), "r"(b[0]), "r"(b[1]));
}

// ---------------------------------------------------------------------------
// Split hidden states fp32 -> bf16 hi/lo
// ---------------------------------------------------------------------------
__global__ void convert_a_kernel(const float* __restrict__ A) {
    size_t i = ((size_t)blockIdx.x * 256 + threadIdx.x) * 4;
    float4 x = *(const float4*)(A + i);
    __nv_bfloat16 h0 = __float2bfloat16(x.x), h1 = __float2bfloat16(x.y);
    __nv_bfloat16 h2 = __float2bfloat16(x.z), h3 = __float2bfloat16(x.w);
    __nv_bfloat16 l0 = __float2bfloat16(x.x - __bfloat162float(h0));
    __nv_bfloat16 l1 = __float2bfloat16(x.y - __bfloat162float(h1));
    __nv_bfloat16 l2 = __float2bfloat16(x.z - __bfloat162float(h2));
    __nv_bfloat16 l3 = __float2bfloat16(x.w - __bfloat162float(h3));
    union { __nv_bfloat16 b[4]; uint2 u; } ph, pl;
    ph.b[0] = h0; ph.b[1] = h1; ph.b[2] = h2; ph.b[3] = h3;
    pl.b[0] = l0; pl.b[1] = l1; pl.b[2] = l2; pl.b[3] = l3;
    *(uint2*)(g_ah + i) = ph.u;
    *(uint2*)(g_al + i) = pl.u;
}

// ---------------------------------------------------------------------------
// Transpose + split W [K,N] -> W^T [N,K] bf16 hi/lo
// ---------------------------------------------------------------------------
__global__ void convert_w_kernel(const float* __restrict__ Wq,
                                 const float* __restrict__ Wk,
                                 const float* __restrict__ Wv) {
    const int z = blockIdx.z;
    const float* W = (z == 0) ? Wq : ((z == 1) ? Wk : Wv);
    __shared__ float t[32][33];
    const int n0 = blockIdx.x * 32, k0 = blockIdx.y * 32;
    #pragma unroll
    for (int j = 0; j < 32; j += 8)
        t[threadIdx.y + j][threadIdx.x] = W[(size_t)(k0 + threadIdx.y + j) * DIM + n0 + threadIdx.x];
    __syncthreads();
    #pragma unroll
    for (int j = 0; j < 32; j += 8) {
        float v = t[threadIdx.x][threadIdx.y + j];
        __nv_bfloat16 h = __float2bfloat16(v);
        __nv_bfloat16 l = __float2bfloat16(v - __bfloat162float(h));
        size_t o = (size_t)(n0 + threadIdx.y + j) * DIM + k0 + threadIdx.x;
        g_wh[z][o] = h;
        g_wl[z][o] = l;
    }
}

// ---------------------------------------------------------------------------
// HMMA bf16 GEMM (3-term split): C = Ah*Bh + Ah*Bl + Al*Bh, fp32 accum.
// CTA 128x128, 256 threads (8 warps, 2x4 of 64x32), BK=64,
// 2-stage cp.async double buffer (64KB/stage, 128KB) -> 1 CTA/SM, no reg cap.
// Tiles per stage: Ah|Al|Bh|Bl, each 128 x 64 bf16 (16KB), row=128B,
// swizzle: chunk j ^ (row & 7).
// Term-major MMA ordering: acc reuse distance = 16 MMAs.
// ---------------------------------------------------------------------------
#define TILE_B   16384
#define STAGE_B  (4 * TILE_B)     // 64KB
#define KSTAGES  8                // 512 / 64

__global__ void __launch_bounds__(256)
qkv_mma_gemm(const float* __restrict__ bq, const float* __restrict__ bk,
             const float* __restrict__ bv)
{
    extern __shared__ __align__(1024) char dsm[];
    __shared__ float s_bias[128];

    const int tid  = threadIdx.x;
    const int wid  = tid >> 5;
    const int lane = tid & 31;
    const int wm   = wid >> 2;       // 0..1  (64-row slabs)
    const int wn   = wid & 3;        // 0..3  (32-col slabs)
    const int nt   = blockIdx.x & 3;
    const int z    = blockIdx.x >> 2;
    const int mt   = blockIdx.y;

    const uint32_t sbase = smem_u32(dsm);

    const float* bias = (z == 0) ? bq : ((z == 1) ? bk : bv);
    const float scale = (z == 0) ? 0.125f : 1.0f;
    float* outp       = (z == 0) ? g_q : ((z == 1) ? g_k : g_v);
    const __nv_bfloat16* srcs[4] = { g_ah + (size_t)mt * 128 * DIM,
                                     g_al + (size_t)mt * 128 * DIM,
                                     g_wh[z] + (size_t)nt * 128 * DIM,
                                     g_wl[z] + (size_t)nt * 128 * DIM };

    if (tid < 128) s_bias[tid] = bias[nt * 128 + tid];

    // ---- stage loader: 4 tiles x (128 rows x 8 sixteen-byte chunks) ----
    auto load_stage = [&](int kt, int buf) {
        const uint32_t sb = sbase + (uint32_t)buf * STAGE_B;
        #pragma unroll
        for (int tile = 0; tile < 4; ++tile) {
            const __nv_bfloat16* src = srcs[tile] + kt * 64;
            #pragma unroll
            for (int it = 0; it < 4; ++it) {
                const int c = it * 256 + tid;
                const int r = c >> 3, j = c & 7;
                const uint32_t soff = sb + (uint32_t)tile * TILE_B +
                                      (uint32_t)r * 128 + (uint32_t)((j ^ (r & 7)) << 4);
                cp_async16(soff, src + (size_t)r * DIM + j * 8);
            }
        }
        CP_COMMIT();
    };

    float acc[4][4][4];
    #pragma unroll
    for (int mi = 0; mi < 4; ++mi)
        #pragma unroll
        for (int ni = 0; ni < 4; ++ni)
            #pragma unroll
            for (int q = 0; q < 4; ++q) acc[mi][ni][q] = 0.f;

    load_stage(0, 0);

    // ldmatrix address components
    const int arow  = wm * 64 + (lane & 15);                             // + mi*16
    const int ahalf = lane >> 4;                                         // k16 half chunk
    const int brow_base = wn * 32 + ((lane >> 3) & 1) * 8 + (lane & 7);  // + np*16
    const int bchunk = lane >> 4;

    for (int kt = 0; kt < KSTAGES; ++kt) {
        if (kt < KSTAGES - 1) {
            load_stage(kt + 1, (kt + 1) & 1);
            CP_WAIT(1);
        } else {
            CP_WAIT(0);
        }
        __syncthreads();

        const uint32_t sb = sbase + (uint32_t)(kt & 1) * STAGE_B;
        const uint32_t aH = sb, aL = sb + TILE_B, bH = sb + 2 * TILE_B, bL = sb + 3 * TILE_B;

        #pragma unroll
        for (int ks = 0; ks < 4; ++ks) {
            uint32_t ahf[4][4], alf[4][4];
            uint32_t bhf[4][2], blf[4][2];
            #pragma unroll
            for (int mi = 0; mi < 4; ++mi) {
                const int r = arow + mi * 16;
                const int j = ks * 2 + ahalf;
                const uint32_t off = (uint32_t)r * 128 + (uint32_t)((j ^ (r & 7)) << 4);
                ldsm_x4(ahf[mi], aH + off);
                ldsm_x4(alf[mi], aL + off);
            }
            #pragma unroll
            for (int np = 0; np < 2; ++np) {     // pairs of n8 blocks
                const int r = brow_base + np * 16;
                const int j = ks * 2 + bchunk;
                const uint32_t off = (uint32_t)r * 128 + (uint32_t)((j ^ (r & 7)) << 4);
                uint32_t th[4], tl[4];
                ldsm_x4(th, bH + off);
                ldsm_x4(tl, bL + off);
                bhf[np * 2 + 0][0] = th[0]; bhf[np * 2 + 0][1] = th[2];
                bhf[np * 2 + 1][0] = th[1]; bhf[np * 2 + 1][1] = th[3];
                blf[np * 2 + 0][0] = tl[0]; blf[np * 2 + 0][1] = tl[2];
                blf[np * 2 + 1][0] = tl[1]; blf[np * 2 + 1][1] = tl[3];
            }
            // term-major ordering: acc reuse distance = 16 MMAs
            #pragma unroll
            for (int mi = 0; mi < 4; ++mi)
                #pragma unroll
                for (int ni = 0; ni < 4; ++ni)
                    mma16816(acc[mi][ni], ahf[mi], bhf[ni]);
            #pragma unroll
            for (int mi = 0; mi < 4; ++mi)
                #pragma unroll
                for (int ni = 0; ni < 4; ++ni)
                    mma16816(acc[mi][ni], ahf[mi], blf[ni]);
            #pragma unroll
            for (int mi = 0; mi < 4; ++mi)
                #pragma unroll
                for (int ni = 0; ni < 4; ++ni)
                    mma16816(acc[mi][ni], alf[mi], bhf[ni]);
        }
        __syncthreads();
    }

    // ---- epilogue: bias + scale, scatter to head-major [B,H,L,DH] ----
    const int g = lane >> 2, tig = lane & 3;
    #pragma unroll
    for (int mi = 0; mi < 4; ++mi) {
        #pragma unroll
        for (int half = 0; half < 2; ++half) {
            const int m = mt * 128 + wm * 64 + mi * 16 + g + half * 8;
            const int b = m >> 13;
            const int l = m & (LL - 1);
            #pragma unroll
            for (int ni = 0; ni < 4; ++ni) {
                const int nl = wn * 32 + ni * 8 + 2 * tig;
                const int n  = nt * 128 + nl;
                const int h  = n >> 6, d = n & 63;
                float2 r2;
                r2.x = (acc[mi][ni][half * 2 + 0] + s_bias[nl + 0]) * scale;
                r2.y = (acc[mi][ni][half * 2 + 1] + s_bias[nl + 1]) * scale;
                *(float2*)&outp[(((size_t)b * NH + h) * LL + l) * DH + d] = r2;
            }
        }
    }
}

// ---------------------------------------------------------------------------
// NA1D attention (unchanged)
// ---------------------------------------------------------------------------
#define QT   128
#define SPAN 152
#define PAD  68

__global__ void __launch_bounds__(128, 4)
na1d_kernel(const float* __restrict__ rpb, float* __restrict__ out)
{
    __shared__ float kv[SPAN][PAD];
    __shared__ float s_rpb[2 * KS - 1];

    const int tid = threadIdx.x;
    const int bh  = blockIdx.y;
    const int b   = bh >> 3;
    const int h   = bh & 7;
    const int l0  = blockIdx.x << 7;
    const int i   = l0 + tid;

    if (tid < 2 * KS - 1) s_rpb[tid] = rpb[h * (2 * KS - 1) + tid];

    int ws, ps;
    if (i < NS * DIL) {
        ws = i & 1;
        ps = (KS - 1) - (i >> 1);
    } else if (i + NS * DIL >= LL) {
        ws = LL - KS * DIL + (i & 1);
        ps = (LL - 1 - i) >> 1;
    } else {
        ws = i - NS * DIL;
        ps = NS;
    }

    const int lo = (l0 >= NS * DIL) ? (l0 - NS * DIL) : 0;
    const int himax = l0 + QT - 1 + NS * DIL;
    const int hi = (himax <= LL - 1) ? himax : (LL - 1);
    const int n4 = (hi - lo + 1) * (DH / 4);
    const int r0 = ws - lo;
    const size_t base = (size_t)bh * LL * DH;

    {
        const float4* src = (const float4*)(g_k + base + (size_t)lo * DH);
        for (int tt = tid; tt < n4; tt += QT) {
            const int r = tt >> 4, c = tt & 15;
            *(float4*)&kv[r][c << 2] = src[tt];
        }
    }
    float4 q[16];
    {
        const float4* qp = (const float4*)(g_q + base + (size_t)i * DH);
        #pragma unroll
        for (int d = 0; d < 16; ++d) q[d] = qp[d];
    }
    __syncthreads();

    float sc[KS];
    #pragma unroll
    for (int j = 0; j < KS; ++j) {
        const float* kr = kv[r0 + DIL * j];
        float s = 0.f;
        #pragma unroll
        for (int d = 0; d < 16; ++d) {
            const float4 k4 = *(const float4*)&kr[d << 2];
            s = fmaf(q[d].x, k4.x, s);
            s = fmaf(q[d].y, k4.y, s);
            s = fmaf(q[d].z, k4.z, s);
            s = fmaf(q[d].w, k4.w, s);
        }
        sc[j] = s + s_rpb[ps + j];
    }

    float mx = sc[0];
    #pragma unroll
    for (int j = 1; j < KS; ++j) mx = fmaxf(mx, sc[j]);
    float sum = 0.f;
    #pragma unroll
    for (int j = 0; j < KS; ++j) { sc[j] = __expf(sc[j] - mx); sum += sc[j]; }
    const float rinv = 1.f / sum;

    __syncthreads();

    {
        const float4* src = (const float4*)(g_v + base + (size_t)lo * DH);
        for (int tt = tid; tt < n4; tt += QT) {
            const int r = tt >> 4, c = tt & 15;
            *(float4*)&kv[r][c << 2] = src[tt];
        }
    }
    __syncthreads();

    float4 o[16];
    #pragma unroll
    for (int d = 0; d < 16; ++d) o[d] = make_float4(0.f, 0.f, 0.f, 0.f);

    #pragma unroll
    for (int j = 0; j < KS; ++j) {
        const float p = sc[j];
        const float* vr = kv[r0 + DIL * j];
        #pragma unroll
        for (int d = 0; d < 16; ++d) {
            const float4 v4 = *(const float4*)&vr[d << 2];
            o[d].x = fmaf(p, v4.x, o[d].x);
            o[d].y = fmaf(p, v4.y, o[d].y);
            o[d].z = fmaf(p, v4.z, o[d].z);
            o[d].w = fmaf(p, v4.w, o[d].w);
        }
    }

    float* op = out + ((size_t)b * LL + i) * DIM + h * DH;
    #pragma unroll
    for (int d = 0; d < 16; ++d) {
        float4 r = o[d];
        r.x *= rinv; r.y *= rinv; r.z *= rinv; r.w *= rinv;
        *(float4*)&op[d << 2] = r;
    }
}

// ---------------------------------------------------------------------------
extern "C" void kernel_launch(void* const* d_in, const int* in_sizes, int n_in,
                              void* d_out, int out_size)
{
    const float* hs  = (const float*)d_in[0];
    const float* Wq  = (const float*)d_in[1];
    const float* bq  = (const float*)d_in[2];
    const float* Wk  = (const float*)d_in[3];
    const float* bk  = (const float*)d_in[4];
    const float* Wv  = (const float*)d_in[5];
    const float* bv  = (const float*)d_in[6];
    const float* rpb = (const float*)d_in[7];
    float* out = (float*)d_out;

    const int dyn_smem = 2 * STAGE_B;   // 128KB
    cudaFuncSetAttribute(qkv_mma_gemm, cudaFuncAttributeMaxDynamicSharedMemorySize, dyn_smem);

    convert_a_kernel<<<32768, 256>>>(hs);
    convert_w_kernel<<<dim3(16, 16, 3), dim3(32, 8)>>>(Wq, Wk, Wv);
    qkv_mma_gemm<<<dim3(12, 512), 256, dyn_smem>>>(bq, bk, bv);
    na1d_kernel<<<dim3(LL / QT, BB * NH), 128>>>(rpb, out);
}

// round 8
// speedup vs baseline: 1.6619x; 1.1261x over previous
#include <cuda_runtime.h>
#include <cuda_bf16.h>
#include <cstdint>

#define BB   8
#define LL   8192
#define DIM  512
#define NH   8
#define DH   64
#define KS   13
#define NS   6
#define DIL  2

// ---------------------------------------------------------------------------
// Device scratch (static only)
// ---------------------------------------------------------------------------
__device__ float g_q[(size_t)BB * NH * LL * DH];
__device__ float g_k[(size_t)BB * NH * LL * DH];
__device__ float g_v[(size_t)BB * NH * LL * DH];
__device__ __nv_bfloat16 g_ah[(size_t)BB * LL * DIM];   // hidden hi split [M,K]
__device__ __nv_bfloat16 g_al[(size_t)BB * LL * DIM];   // hidden lo split
__device__ __nv_bfloat16 g_wh[3][DIM * DIM];            // W^T hi  [N,K]
__device__ __nv_bfloat16 g_wl[3][DIM * DIM];            // W^T lo  [N,K]

// ---------------------------------------------------------------------------
// Baseline-PTX helpers
// ---------------------------------------------------------------------------
__device__ __forceinline__ uint32_t smem_u32(const void* p) {
    uint32_t a;
    asm("{ .reg .u64 t; cvta.to.shared.u64 t, %1; cvt.u32.u64 %0, t; }" : "=r"(a) : "l"(p));
    return a;
}
__device__ __forceinline__ void cp_async16(uint32_t saddr, const void* gptr) {
    asm volatile("cp.async.cg.shared.global [%0], [%1], 16;"
                 :: "r"(saddr), "l"(__cvta_generic_to_global(gptr)) : "memory");
}
#define CP_COMMIT() asm volatile("cp.async.commit_group;" ::: "memory")
#define CP_WAIT(n)  asm volatile("cp.async.wait_group %0;" :: "n"(n) : "memory")

__device__ __forceinline__ void ldsm_x4(uint32_t* r, uint32_t addr) {
    asm volatile("ldmatrix.sync.aligned.m8n8.x4.shared.b16 {%0,%1,%2,%3}, [%4];"
                 : "=r"(r[0]), "=r"(r[1]), "=r"(r[2]), "=r"(r[3]) : "r"(addr));
}
__device__ __forceinline__ void ldsm_x2(uint32_t* r, uint32_t addr) {
    asm volatile("ldmatrix.sync.aligned.m8n8.x2.shared.b16 {%0,%1}, [%2];"
                 : "=r"(r[0]), "=r"(r[1]) : "r"(addr));
}
__device__ __forceinline__ void mma16816(float* c, const uint32_t* a, const uint32_t* b) {
    asm volatile("mma.sync.aligned.m16n8k16.row.col.f32.bf16.bf16.f32 "
                 "{%0,%1,%2,%3}, {%4,%5,%6,%7}, {%8,%9}, {%0,%1,%2,%3};"
                 : "+f"(c[0]), "+f"(c[1]), "+f"(c[2]), "+f"(c[3])
                 : "r"(a[0]), "r"(a[1]), "r"(a[2]), "r"(a[3]), "r"(b[0]), "r"(b[1]));
}

// ---------------------------------------------------------------------------
// Split hidden states fp32 -> bf16 hi/lo
// ---------------------------------------------------------------------------
__global__ void convert_a_kernel(const float* __restrict__ A) {
    size_t i = ((size_t)blockIdx.x * 256 + threadIdx.x) * 4;
    float4 x = *(const float4*)(A + i);
    __nv_bfloat16 h0 = __float2bfloat16(x.x), h1 = __float2bfloat16(x.y);
    __nv_bfloat16 h2 = __float2bfloat16(x.z), h3 = __float2bfloat16(x.w);
    __nv_bfloat16 l0 = __float2bfloat16(x.x - __bfloat162float(h0));
    __nv_bfloat16 l1 = __float2bfloat16(x.y - __bfloat162float(h1));
    __nv_bfloat16 l2 = __float2bfloat16(x.z - __bfloat162float(h2));
    __nv_bfloat16 l3 = __float2bfloat16(x.w - __bfloat162float(h3));
    union { __nv_bfloat16 b[4]; uint2 u; } ph, pl;
    ph.b[0] = h0; ph.b[1] = h1; ph.b[2] = h2; ph.b[3] = h3;
    pl.b[0] = l0; pl.b[1] = l1; pl.b[2] = l2; pl.b[3] = l3;
    *(uint2*)(g_ah + i) = ph.u;
    *(uint2*)(g_al + i) = pl.u;
}

// ---------------------------------------------------------------------------
// Transpose + split W [K,N] -> W^T [N,K] bf16 hi/lo
// ---------------------------------------------------------------------------
__global__ void convert_w_kernel(const float* __restrict__ Wq,
                                 const float* __restrict__ Wk,
                                 const float* __restrict__ Wv) {
    const int z = blockIdx.z;
    const float* W = (z == 0) ? Wq : ((z == 1) ? Wk : Wv);
    __shared__ float t[32][33];
    const int n0 = blockIdx.x * 32, k0 = blockIdx.y * 32;
    #pragma unroll
    for (int j = 0; j < 32; j += 8)
        t[threadIdx.y + j][threadIdx.x] = W[(size_t)(k0 + threadIdx.y + j) * DIM + n0 + threadIdx.x];
    __syncthreads();
    #pragma unroll
    for (int j = 0; j < 32; j += 8) {
        float v = t[threadIdx.x][threadIdx.y + j];
        __nv_bfloat16 h = __float2bfloat16(v);
        __nv_bfloat16 l = __float2bfloat16(v - __bfloat162float(h));
        size_t o = (size_t)(n0 + threadIdx.y + j) * DIM + k0 + threadIdx.x;
        g_wh[z][o] = h;
        g_wl[z][o] = l;
    }
}

// ---------------------------------------------------------------------------
// HMMA bf16 GEMM (3-term split): C = Ah*Bh + Ah*Bl + Al*Bh, fp32 accum.
// Round-3 structure exactly (best measured: GEMM ~730us), ONE change:
// per-mi MMA ordering is ni-major per term -> acc reuse distance 4 MMAs
// (was 1), with the identical register profile (per-mi local A frags).
// CTA 128x128, 256 threads (8 warps, 2x4 of 64x32), BK=64, 2-stage.
// ---------------------------------------------------------------------------
#define TILE_B   16384
#define STAGE_B  (4 * TILE_B)     // 64KB

__global__ void __launch_bounds__(256)
qkv_mma_gemm(const float* __restrict__ bq, const float* __restrict__ bk,
             const float* __restrict__ bv)
{
    extern __shared__ __align__(1024) char dsm[];
    __shared__ float s_bias[128];

    const int tid  = threadIdx.x;
    const int wid  = tid >> 5;
    const int lane = tid & 31;
    const int wm   = wid >> 2;       // 0..1  (64-row slabs)
    const int wn   = wid & 3;        // 0..3  (32-col slabs)
    const int nt   = blockIdx.x & 3;
    const int z    = blockIdx.x >> 2;
    const int mt   = blockIdx.y;

    const uint32_t sbase = smem_u32(dsm);

    const float* bias = (z == 0) ? bq : ((z == 1) ? bk : bv);
    const float scale = (z == 0) ? 0.125f : 1.0f;
    float* outp       = (z == 0) ? g_q : ((z == 1) ? g_k : g_v);
    const __nv_bfloat16* srcs[4] = { g_ah + (size_t)mt * 128 * DIM,
                                     g_al + (size_t)mt * 128 * DIM,
                                     g_wh[z] + (size_t)nt * 128 * DIM,
                                     g_wl[z] + (size_t)nt * 128 * DIM };

    if (tid < 128) s_bias[tid] = bias[nt * 128 + tid];

    // ---- stage loader: 4 tiles, 128 rows x 8 sixteen-byte chunks each ----
    auto load_stage = [&](int kt, int buf) {
        const uint32_t sb = sbase + (uint32_t)buf * STAGE_B;
        #pragma unroll
        for (int tile = 0; tile < 4; ++tile) {
            const __nv_bfloat16* src = srcs[tile] + kt * 64;
            #pragma unroll
            for (int it = 0; it < 4; ++it) {
                const int c = it * 256 + tid;
                const int r = c >> 3, j = c & 7;
                const uint32_t soff = sb + (uint32_t)tile * TILE_B +
                                      (uint32_t)r * 128 + (uint32_t)((j ^ (r & 7)) << 4);
                cp_async16(soff, src + (size_t)r * DIM + j * 8);
            }
        }
        CP_COMMIT();
    };

    float acc[4][4][4];
    #pragma unroll
    for (int mi = 0; mi < 4; ++mi)
        #pragma unroll
        for (int ni = 0; ni < 4; ++ni)
            #pragma unroll
            for (int q = 0; q < 4; ++q) acc[mi][ni][q] = 0.f;

    load_stage(0, 0);

    for (int kt = 0; kt < 8; ++kt) {
        if (kt < 7) load_stage(kt + 1, (kt + 1) & 1);
        if (kt < 7) { CP_WAIT(1); } else { CP_WAIT(0); }
        __syncthreads();

        const uint32_t sb = sbase + (uint32_t)(kt & 1) * STAGE_B;
        const uint32_t aH = sb, aL = sb + TILE_B, bH = sb + 2 * TILE_B, bL = sb + 3 * TILE_B;

        // ldmatrix address row components (round-3 mapping)
        const int arow = wm * 64 + (lane & 15);       // + mi*16
        const int ahalf = lane >> 4;                  // k-chunk half for A
        const int brow = wn * 32 + (lane & 7);        // + ni*8
        const int bhalf = (lane >> 3) & 1;            // k-chunk half for B

        #pragma unroll
        for (int ks = 0; ks < 4; ++ks) {
            uint32_t bhf[4][2], blf[4][2];
            #pragma unroll
            for (int ni = 0; ni < 4; ++ni) {
                const int r = brow + ni * 8;
                const int j = ks * 2 + bhalf;
                const uint32_t off = (uint32_t)r * 128 + (uint32_t)((j ^ (r & 7)) << 4);
                ldsm_x2(bhf[ni], bH + off);
                ldsm_x2(blf[ni], bL + off);
            }
            #pragma unroll
            for (int mi = 0; mi < 4; ++mi) {
                const int r = arow + mi * 16;
                const int j = ks * 2 + ahalf;
                const uint32_t off = (uint32_t)r * 128 + (uint32_t)((j ^ (r & 7)) << 4);
                uint32_t ahf[4], alf[4];
                ldsm_x4(ahf, aH + off);
                ldsm_x4(alf, aL + off);
                // ni-major per term: acc reuse distance = 4 MMAs (was 1)
                #pragma unroll
                for (int ni = 0; ni < 4; ++ni)
                    mma16816(acc[mi][ni], ahf, bhf[ni]);
                #pragma unroll
                for (int ni = 0; ni < 4; ++ni)
                    mma16816(acc[mi][ni], ahf, blf[ni]);
                #pragma unroll
                for (int ni = 0; ni < 4; ++ni)
                    mma16816(acc[mi][ni], alf, bhf[ni]);
            }
        }
        __syncthreads();
    }

    // ---- epilogue: bias + scale, scatter to head-major [B,H,L,DH] ----
    const int g = lane >> 2, tig = lane & 3;
    #pragma unroll
    for (int mi = 0; mi < 4; ++mi) {
        #pragma unroll
        for (int half = 0; half < 2; ++half) {
            const int m = mt * 128 + wm * 64 + mi * 16 + g + half * 8;
            const int b = m >> 13;
            const int l = m & (LL - 1);
            #pragma unroll
            for (int ni = 0; ni < 4; ++ni) {
                const int nl = wn * 32 + ni * 8 + 2 * tig;
                const int n  = nt * 128 + nl;
                const int h  = n >> 6, d = n & 63;
                float2 r2;
                r2.x = (acc[mi][ni][half * 2 + 0] + s_bias[nl + 0]) * scale;
                r2.y = (acc[mi][ni][half * 2 + 1] + s_bias[nl + 1]) * scale;
                *(float2*)&outp[(((size_t)b * NH + h) * LL + l) * DH + d] = r2;
            }
        }
    }
}

// ---------------------------------------------------------------------------
// NA1D attention (unchanged — ~195us)
// ---------------------------------------------------------------------------
#define QT   128
#define SPAN 152
#define PAD  68

__global__ void __launch_bounds__(128, 4)
na1d_kernel(const float* __restrict__ rpb, float* __restrict__ out)
{
    __shared__ float kv[SPAN][PAD];
    __shared__ float s_rpb[2 * KS - 1];

    const int tid = threadIdx.x;
    const int bh  = blockIdx.y;
    const int b   = bh >> 3;
    const int h   = bh & 7;
    const int l0  = blockIdx.x << 7;
    const int i   = l0 + tid;

    if (tid < 2 * KS - 1) s_rpb[tid] = rpb[h * (2 * KS - 1) + tid];

    int ws, ps;
    if (i < NS * DIL) {
        ws = i & 1;
        ps = (KS - 1) - (i >> 1);
    } else if (i + NS * DIL >= LL) {
        ws = LL - KS * DIL + (i & 1);
        ps = (LL - 1 - i) >> 1;
    } else {
        ws = i - NS * DIL;
        ps = NS;
    }

    const int lo = (l0 >= NS * DIL) ? (l0 - NS * DIL) : 0;
    const int himax = l0 + QT - 1 + NS * DIL;
    const int hi = (himax <= LL - 1) ? himax : (LL - 1);
    const int n4 = (hi - lo + 1) * (DH / 4);
    const int r0 = ws - lo;
    const size_t base = (size_t)bh * LL * DH;

    {
        const float4* src = (const float4*)(g_k + base + (size_t)lo * DH);
        for (int tt = tid; tt < n4; tt += QT) {
            const int r = tt >> 4, c = tt & 15;
            *(float4*)&kv[r][c << 2] = src[tt];
        }
    }
    float4 q[16];
    {
        const float4* qp = (const float4*)(g_q + base + (size_t)i * DH);
        #pragma unroll
        for (int d = 0; d < 16; ++d) q[d] = qp[d];
    }
    __syncthreads();

    float sc[KS];
    #pragma unroll
    for (int j = 0; j < KS; ++j) {
        const float* kr = kv[r0 + DIL * j];
        float s = 0.f;
        #pragma unroll
        for (int d = 0; d < 16; ++d) {
            const float4 k4 = *(const float4*)&kr[d << 2];
            s = fmaf(q[d].x, k4.x, s);
            s = fmaf(q[d].y, k4.y, s);
            s = fmaf(q[d].z, k4.z, s);
            s = fmaf(q[d].w, k4.w, s);
        }
        sc[j] = s + s_rpb[ps + j];
    }

    float mx = sc[0];
    #pragma unroll
    for (int j = 1; j < KS; ++j) mx = fmaxf(mx, sc[j]);
    float sum = 0.f;
    #pragma unroll
    for (int j = 0; j < KS; ++j) { sc[j] = __expf(sc[j] - mx); sum += sc[j]; }
    const float rinv = 1.f / sum;

    __syncthreads();

    {
        const float4* src = (const float4*)(g_v + base + (size_t)lo * DH);
        for (int tt = tid; tt < n4; tt += QT) {
            const int r = tt >> 4, c = tt & 15;
            *(float4*)&kv[r][c << 2] = src[tt];
        }
    }
    __syncthreads();

    float4 o[16];
    #pragma unroll
    for (int d = 0; d < 16; ++d) o[d] = make_float4(0.f, 0.f, 0.f, 0.f);

    #pragma unroll
    for (int j = 0; j < KS; ++j) {
        const float p = sc[j];
        const float* vr = kv[r0 + DIL * j];
        #pragma unroll
        for (int d = 0; d < 16; ++d) {
            const float4 v4 = *(const float4*)&vr[d << 2];
            o[d].x = fmaf(p, v4.x, o[d].x);
            o[d].y = fmaf(p, v4.y, o[d].y);
            o[d].z = fmaf(p, v4.z, o[d].z);
            o[d].w = fmaf(p, v4.w, o[d].w);
        }
    }

    float* op = out + ((size_t)b * LL + i) * DIM + h * DH;
    #pragma unroll
    for (int d = 0; d < 16; ++d) {
        float4 r = o[d];
        r.x *= rinv; r.y *= rinv; r.z *= rinv; r.w *= rinv;
        *(float4*)&op[d << 2] = r;
    }
}

// ---------------------------------------------------------------------------
extern "C" void kernel_launch(void* const* d_in, const int* in_sizes, int n_in,
                              void* d_out, int out_size)
{
    const float* hs  = (const float*)d_in[0];
    const float* Wq  = (const float*)d_in[1];
    const float* bq  = (const float*)d_in[2];
    const float* Wk  = (const float*)d_in[3];
    const float* bk  = (const float*)d_in[4];
    const float* Wv  = (const float*)d_in[5];
    const float* bv  = (const float*)d_in[6];
    const float* rpb = (const float*)d_in[7];
    float* out = (float*)d_out;

    const int dyn_smem = 2 * STAGE_B;   // 128KB
    cudaFuncSetAttribute(qkv_mma_gemm, cudaFuncAttributeMaxDynamicSharedMemorySize, dyn_smem);

    convert_a_kernel<<<32768, 256>>>(hs);
    convert_w_kernel<<<dim3(16, 16, 3), dim3(32, 8)>>>(Wq, Wk, Wv);
    qkv_mma_gemm<<<dim3(12, 512), 256, dyn_smem>>>(bq, bk, bv);
    na1d_kernel<<<dim3(LL / QT, BB * NH), 128>>>(rpb, out);
}

// round 9
// speedup vs baseline: 1.6785x; 1.0100x over previous
#include <cuda_runtime.h>
#include <cuda_bf16.h>
#include <cstdint>

#define BB   8
#define LL   8192
#define DIM  512
#define NH   8
#define DH   64
#define KS   13
#define NS   6
#define DIL  2

// ---------------------------------------------------------------------------
// Device scratch (static only)
// ---------------------------------------------------------------------------
__device__ float g_q[(size_t)BB * NH * LL * DH];
__device__ float g_k[(size_t)BB * NH * LL * DH];
__device__ float g_v[(size_t)BB * NH * LL * DH];
__device__ __nv_bfloat16 g_ah[(size_t)BB * LL * DIM];   // hidden hi split [M,K]
__device__ __nv_bfloat16 g_al[(size_t)BB * LL * DIM];   // hidden lo split
__device__ __nv_bfloat16 g_wh[3][DIM * DIM];            // W^T hi  [N,K]
__device__ __nv_bfloat16 g_wl[3][DIM * DIM];            // W^T lo  [N,K]

// ---------------------------------------------------------------------------
// Baseline-PTX helpers
// ---------------------------------------------------------------------------
__device__ __forceinline__ uint32_t smem_u32(const void* p) {
    uint32_t a;
    asm("{ .reg .u64 t; cvta.to.shared.u64 t, %1; cvt.u32.u64 %0, t; }" : "=r"(a) : "l"(p));
    return a;
}
__device__ __forceinline__ void cp_async16(uint32_t saddr, const void* gptr) {
    asm volatile("cp.async.cg.shared.global [%0], [%1], 16;"
                 :: "r"(saddr), "l"(__cvta_generic_to_global(gptr)) : "memory");
}
#define CP_COMMIT() asm volatile("cp.async.commit_group;" ::: "memory")
#define CP_WAIT(n)  asm volatile("cp.async.wait_group %0;" :: "n"(n) : "memory")

__device__ __forceinline__ void ldsm_x4(uint32_t* r, uint32_t addr) {
    asm volatile("ldmatrix.sync.aligned.m8n8.x4.shared.b16 {%0,%1,%2,%3}, [%4];"
                 : "=r"(r[0]), "=r"(r[1]), "=r"(r[2]), "=r"(r[3]) : "r"(addr));
}
__device__ __forceinline__ void ldsm_x2(uint32_t* r, uint32_t addr) {
    asm volatile("ldmatrix.sync.aligned.m8n8.x2.shared.b16 {%0,%1}, [%2];"
                 : "=r"(r[0]), "=r"(r[1]) : "r"(addr));
}
__device__ __forceinline__ void mma16816(float* c, const uint32_t* a, const uint32_t* b) {
    asm volatile("mma.sync.aligned.m16n8k16.row.col.f32.bf16.bf16.f32 "
                 "{%0,%1,%2,%3}, {%4,%5,%6,%7}, {%8,%9}, {%0,%1,%2,%3};"
                 : "+f"(c[0]), "+f"(c[1]), "+f"(c[2]), "+f"(c[3])
                 : "r"(a[0]), "r"(a[1]), "r"(a[2]), "r"(a[3]), "r"(b[0]), "r"(b[1]));
}

// ---------------------------------------------------------------------------
// Split hidden states fp32 -> bf16 hi/lo
// ---------------------------------------------------------------------------
__global__ void convert_a_kernel(const float* __restrict__ A) {
    size_t i = ((size_t)blockIdx.x * 256 + threadIdx.x) * 4;
    float4 x = *(const float4*)(A + i);
    __nv_bfloat16 h0 = __float2bfloat16(x.x), h1 = __float2bfloat16(x.y);
    __nv_bfloat16 h2 = __float2bfloat16(x.z), h3 = __float2bfloat16(x.w);
    __nv_bfloat16 l0 = __float2bfloat16(x.x - __bfloat162float(h0));
    __nv_bfloat16 l1 = __float2bfloat16(x.y - __bfloat162float(h1));
    __nv_bfloat16 l2 = __float2bfloat16(x.z - __bfloat162float(h2));
    __nv_bfloat16 l3 = __float2bfloat16(x.w - __bfloat162float(h3));
    union { __nv_bfloat16 b[4]; uint2 u; } ph, pl;
    ph.b[0] = h0; ph.b[1] = h1; ph.b[2] = h2; ph.b[3] = h3;
    pl.b[0] = l0; pl.b[1] = l1; pl.b[2] = l2; pl.b[3] = l3;
    *(uint2*)(g_ah + i) = ph.u;
    *(uint2*)(g_al + i) = pl.u;
}

// ---------------------------------------------------------------------------
// Transpose + split W [K,N] -> W^T [N,K] bf16 hi/lo
// ---------------------------------------------------------------------------
__global__ void convert_w_kernel(const float* __restrict__ Wq,
                                 const float* __restrict__ Wk,
                                 const float* __restrict__ Wv) {
    const int z = blockIdx.z;
    const float* W = (z == 0) ? Wq : ((z == 1) ? Wk : Wv);
    __shared__ float t[32][33];
    const int n0 = blockIdx.x * 32, k0 = blockIdx.y * 32;
    #pragma unroll
    for (int j = 0; j < 32; j += 8)
        t[threadIdx.y + j][threadIdx.x] = W[(size_t)(k0 + threadIdx.y + j) * DIM + n0 + threadIdx.x];
    __syncthreads();
    #pragma unroll
    for (int j = 0; j < 32; j += 8) {
        float v = t[threadIdx.x][threadIdx.y + j];
        __nv_bfloat16 h = __float2bfloat16(v);
        __nv_bfloat16 l = __float2bfloat16(v - __bfloat162float(h));
        size_t o = (size_t)(n0 + threadIdx.y + j) * DIM + k0 + threadIdx.x;
        g_wh[z][o] = h;
        g_wl[z][o] = l;
    }
}

// ---------------------------------------------------------------------------
// HMMA bf16 GEMM (3-term split): C = Ah*Bh + Ah*Bl + Al*Bh, fp32 accum.
// R3/R8 mainloop unchanged. Pipeline changes only:
//   * 3-stage cp.async ring at BK=64 (64KB/stage, 192KB total, 1 CTA/SM)
//   * ONE __syncthreads per k-stage (trailing barrier provably removable:
//     with 3 stages the kt+2 load only aliases stage (kt-1)%3, and all kt-1
//     LDSMs precede the post-wait barrier in program order).
// ---------------------------------------------------------------------------
#define TILE_B   16384
#define STAGE_B  (4 * TILE_B)     // 64KB
#define NSTG     3
#define KSTAGES  8                // 512 / 64

__global__ void __launch_bounds__(256)
qkv_mma_gemm(const float* __restrict__ bq, const float* __restrict__ bk,
             const float* __restrict__ bv)
{
    extern __shared__ __align__(1024) char dsm[];
    __shared__ float s_bias[128];

    const int tid  = threadIdx.x;
    const int wid  = tid >> 5;
    const int lane = tid & 31;
    const int wm   = wid >> 2;       // 0..1  (64-row slabs)
    const int wn   = wid & 3;        // 0..3  (32-col slabs)
    const int nt   = blockIdx.x & 3;
    const int z    = blockIdx.x >> 2;
    const int mt   = blockIdx.y;

    const uint32_t sbase = smem_u32(dsm);

    const float* bias = (z == 0) ? bq : ((z == 1) ? bk : bv);
    const float scale = (z == 0) ? 0.125f : 1.0f;
    float* outp       = (z == 0) ? g_q : ((z == 1) ? g_k : g_v);
    const __nv_bfloat16* srcs[4] = { g_ah + (size_t)mt * 128 * DIM,
                                     g_al + (size_t)mt * 128 * DIM,
                                     g_wh[z] + (size_t)nt * 128 * DIM,
                                     g_wl[z] + (size_t)nt * 128 * DIM };

    if (tid < 128) s_bias[tid] = bias[nt * 128 + tid];

    // ---- stage loader: 4 tiles, 128 rows x 8 sixteen-byte chunks each ----
    auto load_stage = [&](int kt, int buf) {
        const uint32_t sb = sbase + (uint32_t)buf * STAGE_B;
        #pragma unroll
        for (int tile = 0; tile < 4; ++tile) {
            const __nv_bfloat16* src = srcs[tile] + kt * 64;
            #pragma unroll
            for (int it = 0; it < 4; ++it) {
                const int c = it * 256 + tid;
                const int r = c >> 3, j = c & 7;
                const uint32_t soff = sb + (uint32_t)tile * TILE_B +
                                      (uint32_t)r * 128 + (uint32_t)((j ^ (r & 7)) << 4);
                cp_async16(soff, src + (size_t)r * DIM + j * 8);
            }
        }
        CP_COMMIT();
    };

    float acc[4][4][4];
    #pragma unroll
    for (int mi = 0; mi < 4; ++mi)
        #pragma unroll
        for (int ni = 0; ni < 4; ++ni)
            #pragma unroll
            for (int q = 0; q < 4; ++q) acc[mi][ni][q] = 0.f;

    load_stage(0, 0);
    load_stage(1, 1);

    for (int kt = 0; kt < KSTAGES; ++kt) {
        if (kt < KSTAGES - 1) { CP_WAIT(1); } else { CP_WAIT(0); }
        __syncthreads();
        if (kt + 2 < KSTAGES) load_stage(kt + 2, (kt + 2) % NSTG);

        const uint32_t sb = sbase + (uint32_t)(kt % NSTG) * STAGE_B;
        const uint32_t aH = sb, aL = sb + TILE_B, bH = sb + 2 * TILE_B, bL = sb + 3 * TILE_B;

        // ldmatrix address row components (round-3 mapping)
        const int arow = wm * 64 + (lane & 15);       // + mi*16
        const int ahalf = lane >> 4;                  // k-chunk half for A
        const int brow = wn * 32 + (lane & 7);        // + ni*8
        const int bhalf = (lane >> 3) & 1;            // k-chunk half for B

        #pragma unroll
        for (int ks = 0; ks < 4; ++ks) {
            uint32_t bhf[4][2], blf[4][2];
            #pragma unroll
            for (int ni = 0; ni < 4; ++ni) {
                const int r = brow + ni * 8;
                const int j = ks * 2 + bhalf;
                const uint32_t off = (uint32_t)r * 128 + (uint32_t)((j ^ (r & 7)) << 4);
                ldsm_x2(bhf[ni], bH + off);
                ldsm_x2(blf[ni], bL + off);
            }
            #pragma unroll
            for (int mi = 0; mi < 4; ++mi) {
                const int r = arow + mi * 16;
                const int j = ks * 2 + ahalf;
                const uint32_t off = (uint32_t)r * 128 + (uint32_t)((j ^ (r & 7)) << 4);
                uint32_t ahf[4], alf[4];
                ldsm_x4(ahf, aH + off);
                ldsm_x4(alf, aL + off);
                #pragma unroll
                for (int ni = 0; ni < 4; ++ni)
                    mma16816(acc[mi][ni], ahf, bhf[ni]);
                #pragma unroll
                for (int ni = 0; ni < 4; ++ni)
                    mma16816(acc[mi][ni], ahf, blf[ni]);
                #pragma unroll
                for (int ni = 0; ni < 4; ++ni)
                    mma16816(acc[mi][ni], alf, bhf[ni]);
            }
        }
    }

    // ---- epilogue: bias + scale, scatter to head-major [B,H,L,DH] ----
    const int g = lane >> 2, tig = lane & 3;
    #pragma unroll
    for (int mi = 0; mi < 4; ++mi) {
        #pragma unroll
        for (int half = 0; half < 2; ++half) {
            const int m = mt * 128 + wm * 64 + mi * 16 + g + half * 8;
            const int b = m >> 13;
            const int l = m & (LL - 1);
            #pragma unroll
            for (int ni = 0; ni < 4; ++ni) {
                const int nl = wn * 32 + ni * 8 + 2 * tig;
                const int n  = nt * 128 + nl;
                const int h  = n >> 6, d = n & 63;
                float2 r2;
                r2.x = (acc[mi][ni][half * 2 + 0] + s_bias[nl + 0]) * scale;
                r2.y = (acc[mi][ni][half * 2 + 1] + s_bias[nl + 1]) * scale;
                *(float2*)&outp[(((size_t)b * NH + h) * LL + l) * DH + d] = r2;
            }
        }
    }
}

// ---------------------------------------------------------------------------
// NA1D attention (unchanged — ~195us)
// ---------------------------------------------------------------------------
#define QT   128
#define SPAN 152
#define PAD  68

__global__ void __launch_bounds__(128, 4)
na1d_kernel(const float* __restrict__ rpb, float* __restrict__ out)
{
    __shared__ float kv[SPAN][PAD];
    __shared__ float s_rpb[2 * KS - 1];

    const int tid = threadIdx.x;
    const int bh  = blockIdx.y;
    const int b   = bh >> 3;
    const int h   = bh & 7;
    const int l0  = blockIdx.x << 7;
    const int i   = l0 + tid;

    if (tid < 2 * KS - 1) s_rpb[tid] = rpb[h * (2 * KS - 1) + tid];

    int ws, ps;
    if (i < NS * DIL) {
        ws = i & 1;
        ps = (KS - 1) - (i >> 1);
    } else if (i + NS * DIL >= LL) {
        ws = LL - KS * DIL + (i & 1);
        ps = (LL - 1 - i) >> 1;
    } else {
        ws = i - NS * DIL;
        ps = NS;
    }

    const int lo = (l0 >= NS * DIL) ? (l0 - NS * DIL) : 0;
    const int himax = l0 + QT - 1 + NS * DIL;
    const int hi = (himax <= LL - 1) ? himax : (LL - 1);
    const int n4 = (hi - lo + 1) * (DH / 4);
    const int r0 = ws - lo;
    const size_t base = (size_t)bh * LL * DH;

    {
        const float4* src = (const float4*)(g_k + base + (size_t)lo * DH);
        for (int tt = tid; tt < n4; tt += QT) {
            const int r = tt >> 4, c = tt & 15;
            *(float4*)&kv[r][c << 2] = src[tt];
        }
    }
    float4 q[16];
    {
        const float4* qp = (const float4*)(g_q + base + (size_t)i * DH);
        #pragma unroll
        for (int d = 0; d < 16; ++d) q[d] = qp[d];
    }
    __syncthreads();

    float sc[KS];
    #pragma unroll
    for (int j = 0; j < KS; ++j) {
        const float* kr = kv[r0 + DIL * j];
        float s = 0.f;
        #pragma unroll
        for (int d = 0; d < 16; ++d) {
            const float4 k4 = *(const float4*)&kr[d << 2];
            s = fmaf(q[d].x, k4.x, s);
            s = fmaf(q[d].y, k4.y, s);
            s = fmaf(q[d].z, k4.z, s);
            s = fmaf(q[d].w, k4.w, s);
        }
        sc[j] = s + s_rpb[ps + j];
    }

    float mx = sc[0];
    #pragma unroll
    for (int j = 1; j < KS; ++j) mx = fmaxf(mx, sc[j]);
    float sum = 0.f;
    #pragma unroll
    for (int j = 0; j < KS; ++j) { sc[j] = __expf(sc[j] - mx); sum += sc[j]; }
    const float rinv = 1.f / sum;

    __syncthreads();

    {
        const float4* src = (const float4*)(g_v + base + (size_t)lo * DH);
        for (int tt = tid; tt < n4; tt += QT) {
            const int r = tt >> 4, c = tt & 15;
            *(float4*)&kv[r][c << 2] = src[tt];
        }
    }
    __syncthreads();

    float4 o[16];
    #pragma unroll
    for (int d = 0; d < 16; ++d) o[d] = make_float4(0.f, 0.f, 0.f, 0.f);

    #pragma unroll
    for (int j = 0; j < KS; ++j) {
        const float p = sc[j];
        const float* vr = kv[r0 + DIL * j];
        #pragma unroll
        for (int d = 0; d < 16; ++d) {
            const float4 v4 = *(const float4*)&vr[d << 2];
            o[d].x = fmaf(p, v4.x, o[d].x);
            o[d].y = fmaf(p, v4.y, o[d].y);
            o[d].z = fmaf(p, v4.z, o[d].z);
            o[d].w = fmaf(p, v4.w, o[d].w);
        }
    }

    float* op = out + ((size_t)b * LL + i) * DIM + h * DH;
    #pragma unroll
    for (int d = 0; d < 16; ++d) {
        float4 r = o[d];
        r.x *= rinv; r.y *= rinv; r.z *= rinv; r.w *= rinv;
        *(float4*)&op[d << 2] = r;
    }
}

// ---------------------------------------------------------------------------
extern "C" void kernel_launch(void* const* d_in, const int* in_sizes, int n_in,
                              void* d_out, int out_size)
{
    const float* hs  = (const float*)d_in[0];
    const float* Wq  = (const float*)d_in[1];
    const float* bq  = (const float*)d_in[2];
    const float* Wk  = (const float*)d_in[3];
    const float* bk  = (const float*)d_in[4];
    const float* Wv  = (const float*)d_in[5];
    const float* bv  = (const float*)d_in[6];
    const float* rpb = (const float*)d_in[7];
    float* out = (float*)d_out;

    const int dyn_smem = NSTG * STAGE_B;   // 192KB
    cudaFuncSetAttribute(qkv_mma_gemm, cudaFuncAttributeMaxDynamicSharedMemorySize, dyn_smem);

    convert_a_kernel<<<32768, 256>>>(hs);
    convert_w_kernel<<<dim3(16, 16, 3), dim3(32, 8)>>>(Wq, Wk, Wv);
    qkv_mma_gemm<<<dim3(12, 512), 256, dyn_smem>>>(bq, bk, bv);
    na1d_kernel<<<dim3(LL / QT, BB * NH), 128>>>(rpb, out);
}

// round 10
// speedup vs baseline: 2.0883x; 1.2442x over previous
#include <cuda_runtime.h>
#include <cuda_fp16.h>
#include <cstdint>

#define BB   8
#define LL   8192
#define DIM  512
#define NH   8
#define DH   64
#define KS   13
#define NS   6
#define DIL  2

// ---------------------------------------------------------------------------
// Device scratch (static only)
// ---------------------------------------------------------------------------
__device__ float g_q[(size_t)BB * NH * LL * DH];
__device__ float g_k[(size_t)BB * NH * LL * DH];
__device__ float g_v[(size_t)BB * NH * LL * DH];
__device__ __half g_ah[(size_t)BB * LL * DIM];   // hidden hi split [M,K] fp16
__device__ __half g_al[(size_t)BB * LL * DIM];   // hidden lo split (A - Ah)
__device__ __half g_wh[3][DIM * DIM];            // W^T fp16  [N,K]

// ---------------------------------------------------------------------------
// Baseline-PTX helpers
// ---------------------------------------------------------------------------
__device__ __forceinline__ uint32_t smem_u32(const void* p) {
    uint32_t a;
    asm("{ .reg .u64 t; cvta.to.shared.u64 t, %1; cvt.u32.u64 %0, t; }" : "=r"(a) : "l"(p));
    return a;
}
__device__ __forceinline__ void cp_async16(uint32_t saddr, const void* gptr) {
    asm volatile("cp.async.cg.shared.global [%0], [%1], 16;"
                 :: "r"(saddr), "l"(__cvta_generic_to_global(gptr)) : "memory");
}
#define CP_COMMIT() asm volatile("cp.async.commit_group;" ::: "memory")
#define CP_WAIT(n)  asm volatile("cp.async.wait_group %0;" :: "n"(n) : "memory")

__device__ __forceinline__ void ldsm_x4(uint32_t* r, uint32_t addr) {
    asm volatile("ldmatrix.sync.aligned.m8n8.x4.shared.b16 {%0,%1,%2,%3}, [%4];"
                 : "=r"(r[0]), "=r"(r[1]), "=r"(r[2]), "=r"(r[3]) : "r"(addr));
}
__device__ __forceinline__ void ldsm_x2(uint32_t* r, uint32_t addr) {
    asm volatile("ldmatrix.sync.aligned.m8n8.x2.shared.b16 {%0,%1}, [%2];"
                 : "=r"(r[0]), "=r"(r[1]) : "r"(addr));
}
__device__ __forceinline__ void mma16816(float* c, const uint32_t* a, const uint32_t* b) {
    asm volatile("mma.sync.aligned.m16n8k16.row.col.f32.f16.f16.f32 "
                 "{%0,%1,%2,%3}, {%4,%5,%6,%7}, {%8,%9}, {%0,%1,%2,%3};"
                 : "+f"(c[0]), "+f"(c[1]), "+f"(c[2]), "+f"(c[3])
                 : "r"(a[0]), "r"(a[1]), "r"(a[2]), "r"(a[3]), "r"(b[0]), "r"(b[1]));
}

// ---------------------------------------------------------------------------
// Split hidden states fp32 -> fp16 hi/lo  (A = Ah + Al exact to ~22 bits)
// ---------------------------------------------------------------------------
__global__ void convert_a_kernel(const float* __restrict__ A) {
    size_t i = ((size_t)blockIdx.x * 256 + threadIdx.x) * 4;
    float4 x = *(const float4*)(A + i);
    __half h0 = __float2half_rn(x.x), h1 = __float2half_rn(x.y);
    __half h2 = __float2half_rn(x.z), h3 = __float2half_rn(x.w);
    __half l0 = __float2half_rn(x.x - __half2float(h0));
    __half l1 = __float2half_rn(x.y - __half2float(h1));
    __half l2 = __float2half_rn(x.z - __half2float(h2));
    __half l3 = __float2half_rn(x.w - __half2float(h3));
    union { __half b[4]; uint2 u; } ph, pl;
    ph.b[0] = h0; ph.b[1] = h1; ph.b[2] = h2; ph.b[3] = h3;
    pl.b[0] = l0; pl.b[1] = l1; pl.b[2] = l2; pl.b[3] = l3;
    *(uint2*)(g_ah + i) = ph.u;
    *(uint2*)(g_al + i) = pl.u;
}

// ---------------------------------------------------------------------------
// Transpose W [K,N] -> W^T [N,K] fp16
// ---------------------------------------------------------------------------
__global__ void convert_w_kernel(const float* __restrict__ Wq,
                                 const float* __restrict__ Wk,
                                 const float* __restrict__ Wv) {
    const int z = blockIdx.z;
    const float* W = (z == 0) ? Wq : ((z == 1) ? Wk : Wv);
    __shared__ float t[32][33];
    const int n0 = blockIdx.x * 32, k0 = blockIdx.y * 32;
    #pragma unroll
    for (int j = 0; j < 32; j += 8)
        t[threadIdx.y + j][threadIdx.x] = W[(size_t)(k0 + threadIdx.y + j) * DIM + n0 + threadIdx.x];
    __syncthreads();
    #pragma unroll
    for (int j = 0; j < 32; j += 8) {
        float v = t[threadIdx.x][threadIdx.y + j];
        size_t o = (size_t)(n0 + threadIdx.y + j) * DIM + k0 + threadIdx.x;
        g_wh[z][o] = __float2half_rn(v);
    }
}

// ---------------------------------------------------------------------------
// HMMA fp16 GEMM (2-term split): C = Ah*Bh + Al*Bh, fp32 accum.
// CTA 128x128, 256 threads (8 warps, 2x4 of 64x32), BK=64,
// 3-stage cp.async ring; stage = Ah|Al|Bh, each 128x64 fp16 (16KB) = 48KB.
// One __syncthreads per k-stage. MMA count 2/3 of the bf16 3-term version.
// ---------------------------------------------------------------------------
#define TILE_B   16384
#define STAGE_B  (3 * TILE_B)     // 48KB
#define NSTG     3
#define KSTAGES  8                // 512 / 64

__global__ void __launch_bounds__(256)
qkv_mma_gemm(const float* __restrict__ bq, const float* __restrict__ bk,
             const float* __restrict__ bv)
{
    extern __shared__ __align__(1024) char dsm[];
    __shared__ float s_bias[128];

    const int tid  = threadIdx.x;
    const int wid  = tid >> 5;
    const int lane = tid & 31;
    const int wm   = wid >> 2;       // 0..1  (64-row slabs)
    const int wn   = wid & 3;        // 0..3  (32-col slabs)
    const int nt   = blockIdx.x & 3;
    const int z    = blockIdx.x >> 2;
    const int mt   = blockIdx.y;

    const uint32_t sbase = smem_u32(dsm);

    const float* bias = (z == 0) ? bq : ((z == 1) ? bk : bv);
    const float scale = (z == 0) ? 0.125f : 1.0f;
    float* outp       = (z == 0) ? g_q : ((z == 1) ? g_k : g_v);
    const __half* srcs[3] = { g_ah + (size_t)mt * 128 * DIM,
                              g_al + (size_t)mt * 128 * DIM,
                              g_wh[z] + (size_t)nt * 128 * DIM };

    if (tid < 128) s_bias[tid] = bias[nt * 128 + tid];

    // ---- stage loader: 3 tiles, 128 rows x 8 sixteen-byte chunks each ----
    auto load_stage = [&](int kt, int buf) {
        const uint32_t sb = sbase + (uint32_t)buf * STAGE_B;
        #pragma unroll
        for (int tile = 0; tile < 3; ++tile) {
            const __half* src = srcs[tile] + kt * 64;
            #pragma unroll
            for (int it = 0; it < 4; ++it) {
                const int c = it * 256 + tid;
                const int r = c >> 3, j = c & 7;
                const uint32_t soff = sb + (uint32_t)tile * TILE_B +
                                      (uint32_t)r * 128 + (uint32_t)((j ^ (r & 7)) << 4);
                cp_async16(soff, src + (size_t)r * DIM + j * 8);
            }
        }
        CP_COMMIT();
    };

    float acc[4][4][4];
    #pragma unroll
    for (int mi = 0; mi < 4; ++mi)
        #pragma unroll
        for (int ni = 0; ni < 4; ++ni)
            #pragma unroll
            for (int q = 0; q < 4; ++q) acc[mi][ni][q] = 0.f;

    load_stage(0, 0);
    load_stage(1, 1);

    for (int kt = 0; kt < KSTAGES; ++kt) {
        if (kt < KSTAGES - 1) { CP_WAIT(1); } else { CP_WAIT(0); }
        __syncthreads();
        if (kt + 2 < KSTAGES) load_stage(kt + 2, (kt + 2) % NSTG);

        const uint32_t sb = sbase + (uint32_t)(kt % NSTG) * STAGE_B;
        const uint32_t aH = sb, aL = sb + TILE_B, bH = sb + 2 * TILE_B;

        // ldmatrix address row components (round-3 mapping)
        const int arow = wm * 64 + (lane & 15);       // + mi*16
        const int ahalf = lane >> 4;                  // k-chunk half for A
        const int brow = wn * 32 + (lane & 7);        // + ni*8
        const int bhalf = (lane >> 3) & 1;            // k-chunk half for B

        #pragma unroll
        for (int ks = 0; ks < 4; ++ks) {
            uint32_t bhf[4][2];
            #pragma unroll
            for (int ni = 0; ni < 4; ++ni) {
                const int r = brow + ni * 8;
                const int j = ks * 2 + bhalf;
                const uint32_t off = (uint32_t)r * 128 + (uint32_t)((j ^ (r & 7)) << 4);
                ldsm_x2(bhf[ni], bH + off);
            }
            #pragma unroll
            for (int mi = 0; mi < 4; ++mi) {
                const int r = arow + mi * 16;
                const int j = ks * 2 + ahalf;
                const uint32_t off = (uint32_t)r * 128 + (uint32_t)((j ^ (r & 7)) << 4);
                uint32_t ahf[4], alf[4];
                ldsm_x4(ahf, aH + off);
                ldsm_x4(alf, aL + off);
                #pragma unroll
                for (int ni = 0; ni < 4; ++ni)
                    mma16816(acc[mi][ni], ahf, bhf[ni]);
                #pragma unroll
                for (int ni = 0; ni < 4; ++ni)
                    mma16816(acc[mi][ni], alf, bhf[ni]);
            }
        }
    }

    // ---- epilogue: bias + scale, scatter to head-major [B,H,L,DH] ----
    const int g = lane >> 2, tig = lane & 3;
    #pragma unroll
    for (int mi = 0; mi < 4; ++mi) {
        #pragma unroll
        for (int half = 0; half < 2; ++half) {
            const int m = mt * 128 + wm * 64 + mi * 16 + g + half * 8;
            const int b = m >> 13;
            const int l = m & (LL - 1);
            #pragma unroll
            for (int ni = 0; ni < 4; ++ni) {
                const int nl = wn * 32 + ni * 8 + 2 * tig;
                const int n  = nt * 128 + nl;
                const int h  = n >> 6, d = n & 63;
                float2 r2;
                r2.x = (acc[mi][ni][half * 2 + 0] + s_bias[nl + 0]) * scale;
                r2.y = (acc[mi][ni][half * 2 + 1] + s_bias[nl + 1]) * scale;
                *(float2*)&outp[(((size_t)b * NH + h) * LL + l) * DH + d] = r2;
            }
        }
    }
}

// ---------------------------------------------------------------------------
// NA1D attention (unchanged — ~195us)
// ---------------------------------------------------------------------------
#define QT   128
#define SPAN 152
#define PAD  68

__global__ void __launch_bounds__(128, 4)
na1d_kernel(const float* __restrict__ rpb, float* __restrict__ out)
{
    __shared__ float kv[SPAN][PAD];
    __shared__ float s_rpb[2 * KS - 1];

    const int tid = threadIdx.x;
    const int bh  = blockIdx.y;
    const int b   = bh >> 3;
    const int h   = bh & 7;
    const int l0  = blockIdx.x << 7;
    const int i   = l0 + tid;

    if (tid < 2 * KS - 1) s_rpb[tid] = rpb[h * (2 * KS - 1) + tid];

    int ws, ps;
    if (i < NS * DIL) {
        ws = i & 1;
        ps = (KS - 1) - (i >> 1);
    } else if (i + NS * DIL >= LL) {
        ws = LL - KS * DIL + (i & 1);
        ps = (LL - 1 - i) >> 1;
    } else {
        ws = i - NS * DIL;
        ps = NS;
    }

    const int lo = (l0 >= NS * DIL) ? (l0 - NS * DIL) : 0;
    const int himax = l0 + QT - 1 + NS * DIL;
    const int hi = (himax <= LL - 1) ? himax : (LL - 1);
    const int n4 = (hi - lo + 1) * (DH / 4);
    const int r0 = ws - lo;
    const size_t base = (size_t)bh * LL * DH;

    {
        const float4* src = (const float4*)(g_k + base + (size_t)lo * DH);
        for (int tt = tid; tt < n4; tt += QT) {
            const int r = tt >> 4, c = tt & 15;
            *(float4*)&kv[r][c << 2] = src[tt];
        }
    }
    float4 q[16];
    {
        const float4* qp = (const float4*)(g_q + base + (size_t)i * DH);
        #pragma unroll
        for (int d = 0; d < 16; ++d) q[d] = qp[d];
    }
    __syncthreads();

    float sc[KS];
    #pragma unroll
    for (int j = 0; j < KS; ++j) {
        const float* kr = kv[r0 + DIL * j];
        float s = 0.f;
        #pragma unroll
        for (int d = 0; d < 16; ++d) {
            const float4 k4 = *(const float4*)&kr[d << 2];
            s = fmaf(q[d].x, k4.x, s);
            s = fmaf(q[d].y, k4.y, s);
            s = fmaf(q[d].z, k4.z, s);
            s = fmaf(q[d].w, k4.w, s);
        }
        sc[j] = s + s_rpb[ps + j];
    }

    float mx = sc[0];
    #pragma unroll
    for (int j = 1; j < KS; ++j) mx = fmaxf(mx, sc[j]);
    float sum = 0.f;
    #pragma unroll
    for (int j = 0; j < KS; ++j) { sc[j] = __expf(sc[j] - mx); sum += sc[j]; }
    const float rinv = 1.f / sum;

    __syncthreads();

    {
        const float4* src = (const float4*)(g_v + base + (size_t)lo * DH);
        for (int tt = tid; tt < n4; tt += QT) {
            const int r = tt >> 4, c = tt & 15;
            *(float4*)&kv[r][c << 2] = src[tt];
        }
    }
    __syncthreads();

    float4 o[16];
    #pragma unroll
    for (int d = 0; d < 16; ++d) o[d] = make_float4(0.f, 0.f, 0.f, 0.f);

    #pragma unroll
    for (int j = 0; j < KS; ++j) {
        const float p = sc[j];
        const float* vr = kv[r0 + DIL * j];
        #pragma unroll
        for (int d = 0; d < 16; ++d) {
            const float4 v4 = *(const float4*)&vr[d << 2];
            o[d].x = fmaf(p, v4.x, o[d].x);
            o[d].y = fmaf(p, v4.y, o[d].y);
            o[d].z = fmaf(p, v4.z, o[d].z);
            o[d].w = fmaf(p, v4.w, o[d].w);
        }
    }

    float* op = out + ((size_t)b * LL + i) * DIM + h * DH;
    #pragma unroll
    for (int d = 0; d < 16; ++d) {
        float4 r = o[d];
        r.x *= rinv; r.y *= rinv; r.z *= rinv; r.w *= rinv;
        *(float4*)&op[d << 2] = r;
    }
}

// ---------------------------------------------------------------------------
extern "C" void kernel_launch(void* const* d_in, const int* in_sizes, int n_in,
                              void* d_out, int out_size)
{
    const float* hs  = (const float*)d_in[0];
    const float* Wq  = (const float*)d_in[1];
    const float* bq  = (const float*)d_in[2];
    const float* Wk  = (const float*)d_in[3];
    const float* bk  = (const float*)d_in[4];
    const float* Wv  = (const float*)d_in[5];
    const float* bv  = (const float*)d_in[6];
    const float* rpb = (const float*)d_in[7];
    float* out = (float*)d_out;

    const int dyn_smem = NSTG * STAGE_B;   // 144KB
    cudaFuncSetAttribute(qkv_mma_gemm, cudaFuncAttributeMaxDynamicSharedMemorySize, dyn_smem);

    convert_a_kernel<<<32768, 256>>>(hs);
    convert_w_kernel<<<dim3(16, 16, 3), dim3(32, 8)>>>(Wq, Wk, Wv);
    qkv_mma_gemm<<<dim3(12, 512), 256, dyn_smem>>>(bq, bk, bv);
    na1d_kernel<<<dim3(LL / QT, BB * NH), 128>>>(rpb, out);
}

// round 12
// speedup vs baseline: 3.1157x; 1.4920x over previous
#include <cuda_runtime.h>
#include <cuda_fp16.h>
#include <cstdint>

#define BB   8
#define LL   8192
#define DIM  512
#define NH   8
#define DH   64
#define KS   13
#define NS   6
#define DIL  2

// ---------------------------------------------------------------------------
// Device scratch (static only)
// ---------------------------------------------------------------------------
__device__ float g_q[(size_t)BB * NH * LL * DH];
__device__ float g_k[(size_t)BB * NH * LL * DH];
__device__ float g_v[(size_t)BB * NH * LL * DH];
__device__ __half g_ah[(size_t)BB * LL * DIM];   // hidden fp16 [M,K]
__device__ __half g_wh[3][DIM * DIM];            // W^T fp16  [N,K]

// ---------------------------------------------------------------------------
// Baseline-PTX helpers
// ---------------------------------------------------------------------------
__device__ __forceinline__ uint32_t smem_u32(const void* p) {
    uint32_t a;
    asm("{ .reg .u64 t; cvta.to.shared.u64 t, %1; cvt.u32.u64 %0, t; }" : "=r"(a) : "l"(p));
    return a;
}
__device__ __forceinline__ void cp_async16(uint32_t saddr, const void* gptr) {
    asm volatile("cp.async.cg.shared.global [%0], [%1], 16;"
                 :: "r"(saddr), "l"(__cvta_generic_to_global(gptr)) : "memory");
}
#define CP_COMMIT() asm volatile("cp.async.commit_group;" ::: "memory")
#define CP_WAIT(n)  asm volatile("cp.async.wait_group %0;" :: "n"(n) : "memory")

__device__ __forceinline__ void ldsm_x4(uint32_t* r, uint32_t addr) {
    asm volatile("ldmatrix.sync.aligned.m8n8.x4.shared.b16 {%0,%1,%2,%3}, [%4];"
                 : "=r"(r[0]), "=r"(r[1]), "=r"(r[2]), "=r"(r[3]) : "r"(addr));
}
__device__ __forceinline__ void ldsm_x2(uint32_t* r, uint32_t addr) {
    asm volatile("ldmatrix.sync.aligned.m8n8.x2.shared.b16 {%0,%1}, [%2];"
                 : "=r"(r[0]), "=r"(r[1]) : "r"(addr));
}
__device__ __forceinline__ void mma16816(float* c, const uint32_t* a, const uint32_t* b) {
    asm volatile("mma.sync.aligned.m16n8k16.row.col.f32.f16.f16.f32 "
                 "{%0,%1,%2,%3}, {%4,%5,%6,%7}, {%8,%9}, {%0,%1,%2,%3};"
                 : "+f"(c[0]), "+f"(c[1]), "+f"(c[2]), "+f"(c[3])
                 : "r"(a[0]), "r"(a[1]), "r"(a[2]), "r"(a[3]), "r"(b[0]), "r"(b[1]));
}

// ---------------------------------------------------------------------------
// Convert hidden states fp32 -> fp16
// ---------------------------------------------------------------------------
__global__ void convert_a_kernel(const float* __restrict__ A) {
    size_t i = ((size_t)blockIdx.x * 256 + threadIdx.x) * 4;
    float4 x = *(const float4*)(A + i);
    union { __half b[4]; uint2 u; } ph;
    ph.b[0] = __float2half_rn(x.x);
    ph.b[1] = __float2half_rn(x.y);
    ph.b[2] = __float2half_rn(x.z);
    ph.b[3] = __float2half_rn(x.w);
    *(uint2*)(g_ah + i) = ph.u;
}

// ---------------------------------------------------------------------------
// Transpose W [K,N] -> W^T [N,K] fp16
// ---------------------------------------------------------------------------
__global__ void convert_w_kernel(const float* __restrict__ Wq,
                                 const float* __restrict__ Wk,
                                 const float* __restrict__ Wv) {
    const int z = blockIdx.z;
    const float* W = (z == 0) ? Wq : ((z == 1) ? Wk : Wv);
    __shared__ float t[32][33];
    const int n0 = blockIdx.x * 32, k0 = blockIdx.y * 32;
    #pragma unroll
    for (int j = 0; j < 32; j += 8)
        t[threadIdx.y + j][threadIdx.x] = W[(size_t)(k0 + threadIdx.y + j) * DIM + n0 + threadIdx.x];
    __syncthreads();
    #pragma unroll
    for (int j = 0; j < 32; j += 8) {
        float v = t[threadIdx.x][threadIdx.y + j];
        size_t o = (size_t)(n0 + threadIdx.y + j) * DIM + k0 + threadIdx.x;
        g_wh[z][o] = __float2half_rn(v);
    }
}

// ---------------------------------------------------------------------------
// HMMA fp16 GEMM (1-term): C = fp16(A) * fp16(B), fp32 accum.
// CTA 128x128, 256 threads (8 warps, 2x4 of 64x32), BK=64,
// 3-stage cp.async ring; stage = A|B, each 128x64 fp16 (16KB) = 32KB.
// One __syncthreads per k-stage. MMA count 1/3 of the bf16 3-term version.
// ---------------------------------------------------------------------------
#define TILE_B   16384
#define STAGE_B  (2 * TILE_B)     // 32KB
#define NSTG     3
#define KSTAGES  8                // 512 / 64

__global__ void __launch_bounds__(256)
qkv_mma_gemm(const float* __restrict__ bq, const float* __restrict__ bk,
             const float* __restrict__ bv)
{
    extern __shared__ __align__(1024) char dsm[];
    __shared__ float s_bias[128];

    const int tid  = threadIdx.x;
    const int wid  = tid >> 5;
    const int lane = tid & 31;
    const int wm   = wid >> 2;       // 0..1  (64-row slabs)
    const int wn   = wid & 3;        // 0..3  (32-col slabs)
    const int nt   = blockIdx.x & 3;
    const int z    = blockIdx.x >> 2;
    const int mt   = blockIdx.y;

    const uint32_t sbase = smem_u32(dsm);

    const float* bias = (z == 0) ? bq : ((z == 1) ? bk : bv);
    const float scale = (z == 0) ? 0.125f : 1.0f;
    float* outp       = (z == 0) ? g_q : ((z == 1) ? g_k : g_v);
    const __half* srcs[2] = { g_ah + (size_t)mt * 128 * DIM,
                              g_wh[z] + (size_t)nt * 128 * DIM };

    if (tid < 128) s_bias[tid] = bias[nt * 128 + tid];

    // ---- stage loader: 2 tiles, 128 rows x 8 sixteen-byte chunks each ----
    auto load_stage = [&](int kt, int buf) {
        const uint32_t sb = sbase + (uint32_t)buf * STAGE_B;
        #pragma unroll
        for (int tile = 0; tile < 2; ++tile) {
            const __half* src = srcs[tile] + kt * 64;
            #pragma unroll
            for (int it = 0; it < 4; ++it) {
                const int c = it * 256 + tid;
                const int r = c >> 3, j = c & 7;
                const uint32_t soff = sb + (uint32_t)tile * TILE_B +
                                      (uint32_t)r * 128 + (uint32_t)((j ^ (r & 7)) << 4);
                cp_async16(soff, src + (size_t)r * DIM + j * 8);
            }
        }
        CP_COMMIT();
    };

    float acc[4][4][4];
    #pragma unroll
    for (int mi = 0; mi < 4; ++mi)
        #pragma unroll
        for (int ni = 0; ni < 4; ++ni)
            #pragma unroll
            for (int q = 0; q < 4; ++q) acc[mi][ni][q] = 0.f;

    load_stage(0, 0);
    load_stage(1, 1);

    for (int kt = 0; kt < KSTAGES; ++kt) {
        if (kt < KSTAGES - 1) { CP_WAIT(1); } else { CP_WAIT(0); }
        __syncthreads();
        if (kt + 2 < KSTAGES) load_stage(kt + 2, (kt + 2) % NSTG);

        const uint32_t sb = sbase + (uint32_t)(kt % NSTG) * STAGE_B;
        const uint32_t aH = sb, bH = sb + TILE_B;

        // ldmatrix address row components (round-3 mapping)
        const int arow = wm * 64 + (lane & 15);       // + mi*16
        const int ahalf = lane >> 4;                  // k-chunk half for A
        const int brow = wn * 32 + (lane & 7);        // + ni*8
        const int bhalf = (lane >> 3) & 1;            // k-chunk half for B

        #pragma unroll
        for (int ks = 0; ks < 4; ++ks) {
            uint32_t bhf[4][2];
            #pragma unroll
            for (int ni = 0; ni < 4; ++ni) {
                const int r = brow + ni * 8;
                const int j = ks * 2 + bhalf;
                const uint32_t off = (uint32_t)r * 128 + (uint32_t)((j ^ (r & 7)) << 4);
                ldsm_x2(bhf[ni], bH + off);
            }
            #pragma unroll
            for (int mi = 0; mi < 4; ++mi) {
                const int r = arow + mi * 16;
                const int j = ks * 2 + ahalf;
                const uint32_t off = (uint32_t)r * 128 + (uint32_t)((j ^ (r & 7)) << 4);
                uint32_t ahf[4];
                ldsm_x4(ahf, aH + off);
                #pragma unroll
                for (int ni = 0; ni < 4; ++ni)
                    mma16816(acc[mi][ni], ahf, bhf[ni]);
            }
        }
    }

    // ---- epilogue: bias + scale, scatter to head-major [B,H,L,DH] ----
    const int g = lane >> 2, tig = lane & 3;
    #pragma unroll
    for (int mi = 0; mi < 4; ++mi) {
        #pragma unroll
        for (int half = 0; half < 2; ++half) {
            const int m = mt * 128 + wm * 64 + mi * 16 + g + half * 8;
            const int b = m >> 13;
            const int l = m & (LL - 1);
            #pragma unroll
            for (int ni = 0; ni < 4; ++ni) {
                const int nl = wn * 32 + ni * 8 + 2 * tig;
                const int n  = nt * 128 + nl;
                const int h  = n >> 6, d = n & 63;
                float2 r2;
                r2.x = (acc[mi][ni][half * 2 + 0] + s_bias[nl + 0]) * scale;
                r2.y = (acc[mi][ni][half * 2 + 1] + s_bias[nl + 1]) * scale;
                *(float2*)&outp[(((size_t)b * NH + h) * LL + l) * DH + d] = r2;
            }
        }
    }
}

// ---------------------------------------------------------------------------
// NA1D attention (unchanged — ~195us)
// ---------------------------------------------------------------------------
#define QT   128
#define SPAN 152
#define PAD  68

__global__ void __launch_bounds__(128, 4)
na1d_kernel(const float* __restrict__ rpb, float* __restrict__ out)
{
    __shared__ float kv[SPAN][PAD];
    __shared__ float s_rpb[2 * KS - 1];

    const int tid = threadIdx.x;
    const int bh  = blockIdx.y;
    const int b   = bh >> 3;
    const int h   = bh & 7;
    const int l0  = blockIdx.x << 7;
    const int i   = l0 + tid;

    if (tid < 2 * KS - 1) s_rpb[tid] = rpb[h * (2 * KS - 1) + tid];

    int ws, ps;
    if (i < NS * DIL) {
        ws = i & 1;
        ps = (KS - 1) - (i >> 1);
    } else if (i + NS * DIL >= LL) {
        ws = LL - KS * DIL + (i & 1);
        ps = (LL - 1 - i) >> 1;
    } else {
        ws = i - NS * DIL;
        ps = NS;
    }

    const int lo = (l0 >= NS * DIL) ? (l0 - NS * DIL) : 0;
    const int himax = l0 + QT - 1 + NS * DIL;
    const int hi = (himax <= LL - 1) ? himax : (LL - 1);
    const int n4 = (hi - lo + 1) * (DH / 4);
    const int r0 = ws - lo;
    const size_t base = (size_t)bh * LL * DH;

    {
        const float4* src = (const float4*)(g_k + base + (size_t)lo * DH);
        for (int tt = tid; tt < n4; tt += QT) {
            const int r = tt >> 4, c = tt & 15;
            *(float4*)&kv[r][c << 2] = src[tt];
        }
    }
    float4 q[16];
    {
        const float4* qp = (const float4*)(g_q + base + (size_t)i * DH);
        #pragma unroll
        for (int d = 0; d < 16; ++d) q[d] = qp[d];
    }
    __syncthreads();

    float sc[KS];
    #pragma unroll
    for (int j = 0; j < KS; ++j) {
        const float* kr = kv[r0 + DIL * j];
        float s = 0.f;
        #pragma unroll
        for (int d = 0; d < 16; ++d) {
            const float4 k4 = *(const float4*)&kr[d << 2];
            s = fmaf(q[d].x, k4.x, s);
            s = fmaf(q[d].y, k4.y, s);
            s = fmaf(q[d].z, k4.z, s);
            s = fmaf(q[d].w, k4.w, s);
        }
        sc[j] = s + s_rpb[ps + j];
    }

    float mx = sc[0];
    #pragma unroll
    for (int j = 1; j < KS; ++j) mx = fmaxf(mx, sc[j]);
    float sum = 0.f;
    #pragma unroll
    for (int j = 0; j < KS; ++j) { sc[j] = __expf(sc[j] - mx); sum += sc[j]; }
    const float rinv = 1.f / sum;

    __syncthreads();

    {
        const float4* src = (const float4*)(g_v + base + (size_t)lo * DH);
        for (int tt = tid; tt < n4; tt += QT) {
            const int r = tt >> 4, c = tt & 15;
            *(float4*)&kv[r][c << 2] = src[tt];
        }
    }
    __syncthreads();

    float4 o[16];
    #pragma unroll
    for (int d = 0; d < 16; ++d) o[d] = make_float4(0.f, 0.f, 0.f, 0.f);

    #pragma unroll
    for (int j = 0; j < KS; ++j) {
        const float p = sc[j];
        const float* vr = kv[r0 + DIL * j];
        #pragma unroll
        for (int d = 0; d < 16; ++d) {
            const float4 v4 = *(const float4*)&vr[d << 2];
            o[d].x = fmaf(p, v4.x, o[d].x);
            o[d].y = fmaf(p, v4.y, o[d].y);
            o[d].z = fmaf(p, v4.z, o[d].z);
            o[d].w = fmaf(p, v4.w, o[d].w);
        }
    }

    float* op = out + ((size_t)b * LL + i) * DIM + h * DH;
    #pragma unroll
    for (int d = 0; d < 16; ++d) {
        float4 r = o[d];
        r.x *= rinv; r.y *= rinv; r.z *= rinv; r.w *= rinv;
        *(float4*)&op[d << 2] = r;
    }
}

// ---------------------------------------------------------------------------
extern "C" void kernel_launch(void* const* d_in, const int* in_sizes, int n_in,
                              void* d_out, int out_size)
{
    const float* hs  = (const float*)d_in[0];
    const float* Wq  = (const float*)d_in[1];
    const float* bq  = (const float*)d_in[2];
    const float* Wk  = (const float*)d_in[3];
    const float* bk  = (const float*)d_in[4];
    const float* Wv  = (const float*)d_in[5];
    const float* bv  = (const float*)d_in[6];
    const float* rpb = (const float*)d_in[7];
    float* out = (float*)d_out;

    const int dyn_smem = NSTG * STAGE_B;   // 96KB
    cudaFuncSetAttribute(qkv_mma_gemm, cudaFuncAttributeMaxDynamicSharedMemorySize, dyn_smem);

    convert_a_kernel<<<32768, 256>>>(hs);
    convert_w_kernel<<<dim3(16, 16, 3), dim3(32, 8)>>>(Wq, Wk, Wv);
    qkv_mma_gemm<<<dim3(12, 512), 256, dyn_smem>>>(bq, bk, bv);
    na1d_kernel<<<dim3(LL / QT, BB * NH), 128>>>(rpb, out);
}